// round 6
// baseline (speedup 1.0000x reference)
#include <cuda_runtime.h>

#define NROW 4096
#define DIM  1024

// PRNG_SCHEME: 0 = xor-fold bits + xor-word split keys        (R4: 5.7e-3)
//              1 = low-word bits + low-word split keys        (untested)
//              2 = legacy counter-halved                      (R5: 2.79e-3)
//              3 = foldlike split (FULL pair) + xor-fold bits (modern jax source)
#define PRNG_SCHEME 3

// ---------------- scratch (device globals; no allocation allowed) -------------
__device__ float g_dist[NROW * NROW];   // 64 MB distance matrix
__device__ float g_sq[NROW];
__device__ int   g_predArg[NROW];
__device__ float g_c[NROW];
__device__ int   g_flag[NROW];          // confident && (an >= ap)

#define FPINF __int_as_float(0x7f800000)

// ---------------- threefry2x32 (bit-exact vs JAX) ----------------------------
__device__ __forceinline__ unsigned rotl32(unsigned v, int r) {
    return (v << r) | (v >> (32 - r));
}

__device__ __forceinline__ uint2 threefry(unsigned k0, unsigned k1,
                                          unsigned x0, unsigned x1) {
    unsigned ks2 = k0 ^ k1 ^ 0x1BD11BDAu;
    x0 += k0; x1 += k1;
#define TFR(R) { x0 += x1; x1 = rotl32(x1, R); x1 ^= x0; }
    TFR(13) TFR(15) TFR(26) TFR(6)   x0 += k1;  x1 += ks2 + 1u;
    TFR(17) TFR(29) TFR(16) TFR(24)  x0 += ks2; x1 += k0  + 2u;
    TFR(13) TFR(15) TFR(26) TFR(6)   x0 += k0;  x1 += k1  + 3u;
    TFR(17) TFR(29) TFR(16) TFR(24)  x0 += k1;  x1 += ks2 + 4u;
    TFR(13) TFR(15) TFR(26) TFR(6)   x0 += ks2; x1 += k0  + 5u;
#undef TFR
    return make_uint2(x0, x1);
}

// raw 32 random bits for flattened element m of random_bits(key, 32, (4096,4096))
__device__ __forceinline__ unsigned gbits(uint2 key, unsigned m) {
#if PRNG_SCHEME == 0 || PRNG_SCHEME == 3
    uint2 r = threefry(key.x, key.y, 0u, m);   // counter = (hi=0, lo=m)
    return r.x ^ r.y;                          // partitionable 32-bit fold
#elif PRNG_SCHEME == 1
    return threefry(key.x, key.y, 0u, m).y;
#else
    const unsigned HALF = 8388608u;            // legacy: counters halved
    if (m < HALF) return threefry(key.x, key.y, m, m + HALF).x;
    else          return threefry(key.x, key.y, m - HALF, m).y;
#endif
}

__device__ __forceinline__ void get_keys(uint2& kg1, uint2& kg2) {
#if PRNG_SCHEME == 3
    // _threefry_split_foldlike: child key m = BOTH words of tf(parent, 0, m)
    kg1 = threefry(0u, 42u, 0u, 0u);
    kg2 = threefry(0u, 42u, 0u, 1u);
#elif PRNG_SCHEME == 0 || PRNG_SCHEME == 1
    uint2 parent = make_uint2(0u, 42u);
    kg1 = make_uint2(gbits(parent, 0u), gbits(parent, 1u));
    kg2 = make_uint2(gbits(parent, 2u), gbits(parent, 3u));
#else
    uint2 A = threefry(0u, 42u, 0u, 2u);       // legacy split
    uint2 B = threefry(0u, 42u, 1u, 3u);
    kg1 = make_uint2(A.x, B.x);
    kg2 = make_uint2(A.y, B.y);
#endif
}

// order-preserving float -> uint key (no NaNs present)
__device__ __forceinline__ unsigned fkey(float f) {
    unsigned b = __float_as_uint(f);
    return (b & 0x80000000u) ? ~b : (b | 0x80000000u);
}

// ---------------- small prep kernels -----------------------------------------
__global__ void sq_kernel(const float* __restrict__ X) {
    int warp = (blockIdx.x * blockDim.x + threadIdx.x) >> 5;
    int lane = threadIdx.x & 31;
    if (warp >= NROW) return;
    const float* xr = X + (size_t)warp * DIM;
    float s = 0.f;
    for (int k = lane; k < DIM; k += 32) { float v = xr[k]; s = fmaf(v, v, s); }
    for (int o = 16; o > 0; o >>= 1) s += __shfl_xor_sync(0xffffffffu, s, o);
    if (lane == 0) g_sq[warp] = s;
}

__global__ void predarg_kernel(const float* __restrict__ P) {
    int i = blockIdx.x * blockDim.x + threadIdx.x;
    if (i >= NROW) return;
    const float* pr = P + (size_t)i * 64;
    float bv = pr[0]; int bi = 0;
    for (int k = 1; k < 64; k++) { float v = pr[k]; if (v > bv) { bv = v; bi = k; } }
    g_predArg[i] = bi;
}

// ---------------- fp32 tiled GEMM -> dist ------------------------------------
// 128x128 tile per 256-thread block, 8x8 per thread, BK=8
__global__ __launch_bounds__(256) void gemm_dist(const float* __restrict__ X) {
    __shared__ float As[8][132];
    __shared__ float Bs[8][132];
    const int bi = blockIdx.y * 128;
    const int bj = blockIdx.x * 128;
    const int tid = threadIdx.x;
    const int tx = tid & 15, ty = tid >> 4;

    float acc[8][8];
#pragma unroll
    for (int u = 0; u < 8; u++)
#pragma unroll
        for (int v = 0; v < 8; v++) acc[u][v] = 0.f;

    for (int k0 = 0; k0 < DIM; k0 += 8) {
#pragma unroll
        for (int l = 0; l < 4; l++) {
            int lin = tid + l * 256;
            int r = lin >> 3, cc = lin & 7;
            As[cc][r] = X[(size_t)(bi + r) * DIM + k0 + cc];
            Bs[cc][r] = X[(size_t)(bj + r) * DIM + k0 + cc];
        }
        __syncthreads();
#pragma unroll
        for (int kk = 0; kk < 8; kk++) {
            float a[8], b[8];
#pragma unroll
            for (int u = 0; u < 8; u++) { a[u] = As[kk][ty * 8 + u]; b[u] = Bs[kk][tx * 8 + u]; }
#pragma unroll
            for (int u = 0; u < 8; u++)
#pragma unroll
                for (int v = 0; v < 8; v++) acc[u][v] = fmaf(a[u], b[v], acc[u][v]);
        }
        __syncthreads();
    }

#pragma unroll
    for (int u = 0; u < 8; u++) {
        int ii = bi + ty * 8 + u;
        float sqi = g_sq[ii];
#pragma unroll
        for (int v4 = 0; v4 < 2; v4++) {
            int jj = bj + tx * 8 + v4 * 4;
            float4 o;
            float* oc = &o.x;
#pragma unroll
            for (int q = 0; q < 4; q++) {
                float d2 = sqi + g_sq[jj + q] - 2.f * acc[u][v4 * 4 + q];
                oc[q] = sqrtf(fmaxf(d2, 1e-12f));
            }
            *reinterpret_cast<float4*>(&g_dist[(size_t)ii * NROW + jj]) = o;
        }
    }
}

// ---------------- per-row selection + triplet logic ---------------------------
__device__ __forceinline__ long long blockMaxLL(long long v, unsigned long long* red) {
    int tid = threadIdx.x;
    red[tid] = (unsigned long long)(v + 1);   // v >= -1
    __syncthreads();
    for (int s = 128; s > 0; s >>= 1) {
        if (tid < s && red[tid + s] > red[tid]) red[tid] = red[tid + s];
        __syncthreads();
    }
    long long r = (long long)red[0] - 1;
    __syncthreads();
    return r;
}

__global__ __launch_bounds__(256) void row_kernel(
    const float* __restrict__ prob, const int* __restrict__ targets,
    const float* __restrict__ thrp)
{
    __shared__ float row[NROW];
    __shared__ float work[NROW];
    __shared__ unsigned long long red[256];
    __shared__ float s_VA, s_VB, s_IC;
    __shared__ int   s_sel[12];

    const int i = blockIdx.x;
    const int tid = threadIdx.x;
    const float thr = *thrp;
    const int tgt_i = targets[i];
    const float* drow = g_dist + (size_t)i * NROW;

    for (int t = tid; t < NROW; t += 256) { float v = drow[t]; row[t] = v; work[t] = v; }
    __syncthreads();

    // ---- IC: stable top-20 (desc) over cols [64,4096), bugged gather row[pos-64]
    float icsum = 0.f;
    for (int it = 0; it < 20; it++) {
        unsigned long long lb = 0;
        for (int j = 64 + tid; j < NROW; j += 256) {
            unsigned long long comp =
                ((unsigned long long)fkey(work[j]) << 12) | (unsigned)(4095 - j);
            if (comp > lb) lb = comp;
        }
        red[tid] = lb; __syncthreads();
        for (int s = 128; s > 0; s >>= 1) {
            if (tid < s && red[tid + s] > red[tid]) red[tid] = red[tid + s];
            __syncthreads();
        }
        int pos = 4095 - (int)(red[0] & 0xFFFull);
        if (tid == 0) { icsum += row[pos - 64]; work[pos] = -FPINF; }
        __syncthreads();
    }
    if (tid == 0) s_IC = icsum * (1.f / 20.f);

    // ---- VA / VB: stable top-20 in 32-wide slices, bugged relative gather
    if (tid < 2) {
        int base = (tid == 1) ? 32 : 0;
        unsigned mask = 0; float s = 0.f;
        for (int t = 0; t < 20; t++) {
            float bv = 0.f; int bq = -1;
            for (int q = 0; q < 32; q++) {
                if (mask & (1u << q)) continue;
                float v = row[base + q];
                if (bq < 0 || v > bv) { bv = v; bq = q; }
            }
            mask |= 1u << bq;
            s += row[bq];                      // gather at RELATIVE index (the bug)
        }
        if (tid == 0) s_VA = s * (1.f / 20.f); else s_VB = s * (1.f / 20.f);
    }
    __syncthreads();

    // ---- 12 nearest negatives (stable ascending)
    for (int t = tid; t < NROW; t += 256)
        work[t] = (targets[t] != tgt_i) ? row[t] : FPINF;
    __syncthreads();
    for (int it = 0; it < 12; it++) {
        unsigned long long lb = 0;
        for (int j = tid; j < NROW; j += 256) {
            unsigned long long comp =
                ((unsigned long long)(~fkey(work[j])) << 12) | (unsigned)(4095 - j);
            if (comp > lb) lb = comp;
        }
        red[tid] = lb; __syncthreads();
        for (int s = 128; s > 0; s >>= 1) {
            if (tid < s && red[tid + s] > red[tid]) red[tid] = red[tid + s];
            __syncthreads();
        }
        int pos = 4095 - (int)(red[0] & 0xFFFull);
        if (tid == 0) { s_sel[it] = pos; work[pos] = FPINF; }
        __syncthreads();
    }

    // ---- gumbel argmax over class members (monotone in folded bits)
    uint2 kg1, kg2; get_keys(kg1, kg2);
    long long b1 = -1, b2c = -1, b2a = -1;
    for (int j = tid; j < NROW; j += 256) {
        if (j == i || targets[j] != tgt_i) continue;
        unsigned m = (unsigned)(i * NROW + j);
        unsigned u1 = gbits(kg1, m) >> 9;
        unsigned u2 = gbits(kg2, m) >> 9;
        long long c1 = ((long long)u1 << 12) | (long long)(4095 - j);
        long long c2 = ((long long)u2 << 12) | (long long)(4095 - j);
        if (c1 > b1) b1 = c1;
        if (c2 > b2a) b2a = c2;
        if (prob[j] >= thr && c2 > b2c) b2c = c2;
    }
    long long R1  = blockMaxLL(b1,  red);
    long long R2c = blockMaxLL(b2c, red);
    long long R2a = blockMaxLL(b2a, red);
    int p_idx = (R1 >= 0) ? (4095 - (int)(R1 & 0xFFF)) : i;
    int p_new = (R2c >= 0) ? (4095 - (int)(R2c & 0xFFF))
               : ((R2a >= 0) ? (4095 - (int)(R2a & 0xFFF)) : i);

    // ---- final per-row triplet logic (thread 0)
    if (tid == 0) {
        const float margin = 0.3f;
        int hn = s_sel[0];
        int first = 10;
        for (int t = 0; t < 10; t++) {
            if (prob[s_sel[1 + t]] >= thr) { first = t; break; }
        }
        int hn_new = s_sel[1 + first];

        float d_ip      = row[p_idx];
        float d_ihn     = row[hn];
        float d_ihn_new = row[hn_new];
        float d_ipnew   = row[p_new];
        bool conf_p  = prob[p_idx] >= thr;
        bool conf_hn = prob[hn]    >= thr;
        bool FN = (g_predArg[hn] == tgt_i);

        float ap = d_ip, an = d_ihn;
        bool bFN = conf_p && !conf_hn && FN;
        if (bFN) { ap = (d_ip + d_ihn) * 0.5f; an = d_ihn_new; }
        bool cRes = (!conf_p && conf_hn) || (!conf_p && !conf_hn && !FN);
        if (cRes) { an = (d_ip + d_ihn) * 0.5f; ap = d_ipnew; }
        bool inv = !conf_p && !conf_hn && FN;
        float c_conf = inv ? fmaxf(an - ap + margin, 0.f)
                           : fmaxf(ap - an + margin, 0.f);

        float apA = row[min(i + 32, NROW - 1)];
        float apB = row[max(i - 32, 0)];
        float apC = row[i];
        float cA = (fmaxf(apA - s_IC + margin, 0.f) + fmaxf(apA - s_VA + margin, 0.f)) * 0.5f;
        float cB = (fmaxf(apB - s_IC + margin, 0.f) + fmaxf(apB - s_VB + margin, 0.f)) * 0.5f;
        float cC = fmaxf(apC - s_IC + margin, 0.f);
        float c_unconf = (i < 32) ? cA : ((i < 64) ? cB : cC);

        bool confident_i = prob[i] >= thr;
        float c = confident_i ? c_conf : c_unconf;
        g_c[i] = c;
        g_flag[i] = (confident_i && (an >= ap)) ? 1 : 0;
    }
}

// ---------------- deterministic final reduction -------------------------------
__global__ __launch_bounds__(256) void final_kernel(
    const float* __restrict__ prob, const float* __restrict__ thrp,
    float* __restrict__ out, int out_size)
{
    __shared__ float sred[256];
    __shared__ int   ired[256], ired2[256];
    __shared__ int   s_j;
    int tid = threadIdx.x;
    float thr = *thrp;

    if (tid == 0) {
        int j = -1;
        for (int r = 0; r < 64; r++) if (!(prob[r] >= thr)) j = r;
        s_j = j;
    }
    __syncthreads();
    int j = s_j;

    float ls = 0.f; int cor = 0, cnt = 0;
    for (int r = tid; r < NROW; r += 256) {
        bool conf = prob[r] >= thr;
        bool ovr = (!conf) && (r < 64);
        bool keep = (r > j) && !ovr;
        if (keep) ls += g_c[r];
        if (conf) { cnt++; cor += g_flag[r]; }
    }
    sred[tid] = ls; ired[tid] = cor; ired2[tid] = cnt;
    __syncthreads();
    for (int s = 128; s > 0; s >>= 1) {
        if (tid < s) {
            sred[tid] += sred[tid + s];
            ired[tid] += ired[tid + s];
            ired2[tid] += ired2[tid + s];
        }
        __syncthreads();
    }
    if (tid == 0) {
        float loss = sred[0] + ((j >= 0) ? g_c[j] : 0.f);
        out[0] = loss * (1.f / (float)NROW);
        if (out_size > 1) out[1] = (float)ired[0];
        if (out_size > 2) out[2] = (float)ired2[0];
    }
    for (int t = 3 + tid; t < out_size; t += 256) out[t] = 0.f;
}

// ---------------- launch ------------------------------------------------------
extern "C" void kernel_launch(void* const* d_in, const int* in_sizes, int n_in,
                              void* d_out, int out_size) {
    const float* X       = (const float*)d_in[0];   // inputs (4096,1024) f32
    const float* P       = (const float*)d_in[1];   // prediction (4096,64) f32
    const int*   targets = (const int*)  d_in[2];   // targets (4096) i32
    const float* prob    = (const float*)d_in[4];   // prob (4096) f32
    const float* thr     = (const float*)d_in[5];   // threshold (1) f32
    float* out = (float*)d_out;

    sq_kernel<<<512, 256>>>(X);
    predarg_kernel<<<16, 256>>>(P);
    dim3 g(NROW / 128, NROW / 128);
    gemm_dist<<<g, 256>>>(X);
    row_kernel<<<NROW, 256>>>(prob, targets, thr);
    final_kernel<<<1, 256>>>(prob, thr, out, out_size);
}

// round 8
// speedup vs baseline: 2.4721x; 2.4721x over previous
#include <cuda_runtime.h>
#include <cuda_bf16.h>

#define NROW 4096
#define DIM  1024

// ---------------- scratch (device globals; no allocation allowed) -------------
__device__ float g_dist[NROW * NROW];            // 64 MB distance matrix
__device__ __nv_bfloat16 g_Ah[NROW * DIM];       // 8 MB hi split
__device__ __nv_bfloat16 g_Al[NROW * DIM];       // 8 MB lo split
__device__ float g_sq[NROW];
__device__ int   g_predArg[NROW];
__device__ float g_c[NROW];
__device__ int   g_flag[NROW];

#define FPINF __int_as_float(0x7f800000)
typedef unsigned long long ull;

// ---------------- threefry2x32 (bit-exact vs JAX partitionable) ---------------
__device__ __forceinline__ unsigned rotl32(unsigned v, int r) {
    return (v << r) | (v >> (32 - r));
}

__device__ __forceinline__ uint2 threefry(unsigned k0, unsigned k1,
                                          unsigned x0, unsigned x1) {
    unsigned ks2 = k0 ^ k1 ^ 0x1BD11BDAu;
    x0 += k0; x1 += k1;
#define TFR(R) { x0 += x1; x1 = rotl32(x1, R); x1 ^= x0; }
    TFR(13) TFR(15) TFR(26) TFR(6)   x0 += k1;  x1 += ks2 + 1u;
    TFR(17) TFR(29) TFR(16) TFR(24)  x0 += ks2; x1 += k0  + 2u;
    TFR(13) TFR(15) TFR(26) TFR(6)   x0 += k0;  x1 += k1  + 3u;
    TFR(17) TFR(29) TFR(16) TFR(24)  x0 += k1;  x1 += ks2 + 4u;
    TFR(13) TFR(15) TFR(26) TFR(6)   x0 += ks2; x1 += k0  + 5u;
#undef TFR
    return make_uint2(x0, x1);
}

// partitionable random_bits: counter (hi=0, lo=m), xor-fold of the 64-bit block
__device__ __forceinline__ unsigned gbits(uint2 key, unsigned m) {
    uint2 r = threefry(key.x, key.y, 0u, m);
    return r.x ^ r.y;
}

// order-preserving float -> uint key (no NaNs present)
__device__ __forceinline__ unsigned fkey(float f) {
    unsigned b = __float_as_uint(f);
    return (b & 0x80000000u) ? ~b : (b | 0x80000000u);
}

// ---------------- small prep kernels -----------------------------------------
__global__ void sq_kernel(const float* __restrict__ X) {
    int warp = (blockIdx.x * blockDim.x + threadIdx.x) >> 5;
    int lane = threadIdx.x & 31;
    if (warp >= NROW) return;
    const float* xr = X + (size_t)warp * DIM;
    float s = 0.f;
    for (int k = lane; k < DIM; k += 32) { float v = xr[k]; s = fmaf(v, v, s); }
    for (int o = 16; o > 0; o >>= 1) s += __shfl_xor_sync(0xffffffffu, s, o);
    if (lane == 0) g_sq[warp] = s;
}

__global__ void predarg_kernel(const float* __restrict__ P) {
    int i = blockIdx.x * blockDim.x + threadIdx.x;
    if (i >= NROW) return;
    const float* pr = P + (size_t)i * 64;
    float bv = pr[0]; int bi = 0;
    for (int k = 1; k < 64; k++) { float v = pr[k]; if (v > bv) { bv = v; bi = k; } }
    g_predArg[i] = bi;
}

__global__ void split_kernel(const float* __restrict__ X) {
    int idx = blockIdx.x * blockDim.x + threadIdx.x;
    const float2* x2 = (const float2*)X;
    __nv_bfloat162* ah2 = (__nv_bfloat162*)g_Ah;
    __nv_bfloat162* al2 = (__nv_bfloat162*)g_Al;
    for (int t = idx; t < NROW * DIM / 2; t += gridDim.x * blockDim.x) {
        float2 v = x2[t];
        __nv_bfloat16 h0 = __float2bfloat16(v.x);
        __nv_bfloat16 h1 = __float2bfloat16(v.y);
        __nv_bfloat16 l0 = __float2bfloat16(v.x - __bfloat162float(h0));
        __nv_bfloat16 l1 = __float2bfloat16(v.y - __bfloat162float(h1));
        ah2[t] = __halves2bfloat162(h0, h1);
        al2[t] = __halves2bfloat162(l0, l1);
    }
}

// ---------------- tensor-core split-bf16 GEMM -> dist -------------------------
__device__ __forceinline__ void ldsm_x4(unsigned& r0, unsigned& r1,
                                        unsigned& r2, unsigned& r3, unsigned a) {
    asm volatile("ldmatrix.sync.aligned.m8n8.x4.shared.b16 {%0,%1,%2,%3}, [%4];"
                 : "=r"(r0), "=r"(r1), "=r"(r2), "=r"(r3) : "r"(a));
}
__device__ __forceinline__ void mma_bf16(float* d, const unsigned* a,
                                         unsigned b0, unsigned b1) {
    asm volatile(
        "mma.sync.aligned.m16n8k16.row.col.f32.bf16.bf16.f32 "
        "{%0,%1,%2,%3}, {%4,%5,%6,%7}, {%8,%9}, {%0,%1,%2,%3};"
        : "+f"(d[0]), "+f"(d[1]), "+f"(d[2]), "+f"(d[3])
        : "r"(a[0]), "r"(a[1]), "r"(a[2]), "r"(a[3]), "r"(b0), "r"(b1));
}
__device__ __forceinline__ void cp16(unsigned dst, const void* src) {
    asm volatile("cp.async.cg.shared.global [%0], [%1], 16;" :: "r"(dst), "l"(src));
}

// swizzled byte offset of (row, 16B-half) within a 128x32B tile
__device__ __forceinline__ unsigned sw_off(int row, int half) {
    return (unsigned)(row * 32 + (((half ^ (row >> 2)) & 1) << 4));
}
#define TOFF(s, t) (((s) * 4 + (t)) * 128 * 32)

__global__ __launch_bounds__(256, 2) void gemm_bf16() {
    __shared__ __align__(16) unsigned char smem[2 * 4 * 128 * 32]; // 32 KB
    __shared__ float sqA[128], sqB[128];

    if (blockIdx.x < blockIdx.y) return;   // symmetry: upper blocks only
    const int bi = blockIdx.y * 128;
    const int bj = blockIdx.x * 128;
    const int tid = threadIdx.x;
    const int lane = tid & 31, wid = tid >> 5;
    const int wm = wid >> 2, wn = wid & 3;  // warp tile: 64(m) x 32(n)

    if (tid < 128) { sqA[tid] = g_sq[bi + tid]; sqB[tid] = g_sq[bj + tid]; }

    unsigned sbase = (unsigned)__cvta_generic_to_shared(smem);

    float acc[4][4][4];
#pragma unroll
    for (int a = 0; a < 4; a++)
#pragma unroll
        for (int b = 0; b < 4; b++)
#pragma unroll
            for (int c = 0; c < 4; c++) acc[a][b][c] = 0.f;

    const int lrow = tid >> 1, lhalf = tid & 1;   // loader mapping
    const __nv_bfloat16* srcA_h = g_Ah + (size_t)(bi + lrow) * DIM + lhalf * 8;
    const __nv_bfloat16* srcA_l = g_Al + (size_t)(bi + lrow) * DIM + lhalf * 8;
    const __nv_bfloat16* srcB_h = g_Ah + (size_t)(bj + lrow) * DIM + lhalf * 8;
    const __nv_bfloat16* srcB_l = g_Al + (size_t)(bj + lrow) * DIM + lhalf * 8;
    unsigned dsw = sw_off(lrow, lhalf);

#define LOAD_STAGE(k0, s) {                                   \
        cp16(sbase + TOFF(s, 0) + dsw, srcA_h + (k0));        \
        cp16(sbase + TOFF(s, 1) + dsw, srcA_l + (k0));        \
        cp16(sbase + TOFF(s, 2) + dsw, srcB_h + (k0));        \
        cp16(sbase + TOFF(s, 3) + dsw, srcB_l + (k0));        \
    }

    // A-frag ldmatrix addr pieces (lane-dependent, tile-row varies by mt)
    const int a_r = (lane & 7) + ((lane >> 3) & 1) * 8;   // 0..15 within mtile
    const int a_h = (lane >> 4) & 1;
    // B-frag: lane -> (n within 16-wide pair, half)
    const int b_mat = lane >> 3;
    const int b_n = ((b_mat >> 1) & 1) * 8 + (lane & 7);  // 0..15 within pair
    const int b_h = b_mat & 1;

    LOAD_STAGE(0, 0);
    asm volatile("cp.async.commit_group;");

    for (int ks = 0; ks < 64; ks++) {
        const int cur = ks & 1;
        if (ks < 63) LOAD_STAGE((ks + 1) * 16, (ks + 1) & 1);
        asm volatile("cp.async.commit_group;");
        asm volatile("cp.async.wait_group 1;");
        __syncthreads();

        unsigned ah[4][4], bb[2][4];
        // load A-hi frags
#pragma unroll
        for (int mt = 0; mt < 4; mt++) {
            int r = wm * 64 + mt * 16 + a_r;
            ldsm_x4(ah[mt][0], ah[mt][1], ah[mt][2], ah[mt][3],
                    sbase + TOFF(cur, 0) + sw_off(r, a_h));
        }
        // load B-hi frags (2 ldsm.x4 cover 4 ntiles)
#pragma unroll
        for (int p = 0; p < 2; p++) {
            int n = wn * 32 + p * 16 + b_n;
            ldsm_x4(bb[p][0], bb[p][1], bb[p][2], bb[p][3],
                    sbase + TOFF(cur, 2) + sw_off(n, b_h));
        }
        // hi*hi
#pragma unroll
        for (int mt = 0; mt < 4; mt++)
#pragma unroll
            for (int nt = 0; nt < 4; nt++)
                mma_bf16(acc[mt][nt], ah[mt], bb[nt >> 1][(nt & 1) * 2],
                         bb[nt >> 1][(nt & 1) * 2 + 1]);
        // lo*hi (A-lo, B-hi)
        {
            unsigned al[4][4];
#pragma unroll
            for (int mt = 0; mt < 4; mt++) {
                int r = wm * 64 + mt * 16 + a_r;
                ldsm_x4(al[mt][0], al[mt][1], al[mt][2], al[mt][3],
                        sbase + TOFF(cur, 1) + sw_off(r, a_h));
            }
#pragma unroll
            for (int mt = 0; mt < 4; mt++)
#pragma unroll
                for (int nt = 0; nt < 4; nt++)
                    mma_bf16(acc[mt][nt], al[mt], bb[nt >> 1][(nt & 1) * 2],
                             bb[nt >> 1][(nt & 1) * 2 + 1]);
        }
        // hi*lo (A-hi, B-lo)
#pragma unroll
        for (int p = 0; p < 2; p++) {
            int n = wn * 32 + p * 16 + b_n;
            ldsm_x4(bb[p][0], bb[p][1], bb[p][2], bb[p][3],
                    sbase + TOFF(cur, 3) + sw_off(n, b_h));
        }
#pragma unroll
        for (int mt = 0; mt < 4; mt++)
#pragma unroll
            for (int nt = 0; nt < 4; nt++)
                mma_bf16(acc[mt][nt], ah[mt], bb[nt >> 1][(nt & 1) * 2],
                         bb[nt >> 1][(nt & 1) * 2 + 1]);

        __syncthreads();
    }

    // epilogue: d2 -> sqrt -> store direct + mirror
    const bool diag = (blockIdx.x == blockIdx.y);
    const int r_b = wm * 64 + (lane >> 2);
    const int c_b = wn * 32 + (lane & 3) * 2;
#pragma unroll
    for (int mt = 0; mt < 4; mt++) {
#pragma unroll
        for (int h = 0; h < 2; h++) {
            int r = r_b + mt * 16 + h * 8;
            int ii = bi + r;
            float sqi = sqA[r];
#pragma unroll
            for (int nt = 0; nt < 4; nt++) {
                int c = c_b + nt * 8;
                int jj = bj + c;
                float v0 = sqrtf(fmaxf(sqi + sqB[c]     - 2.f * acc[mt][nt][2 * h],     1e-12f));
                float v1 = sqrtf(fmaxf(sqi + sqB[c + 1] - 2.f * acc[mt][nt][2 * h + 1], 1e-12f));
                float2 o; o.x = v0; o.y = v1;
                *reinterpret_cast<float2*>(&g_dist[(size_t)ii * NROW + jj]) = o;
                if (!diag) {
                    g_dist[(size_t)jj * NROW + ii] = v0;
                    g_dist[(size_t)(jj + 1) * NROW + ii] = v1;
                }
            }
        }
    }
}

// ---------------- per-row selection + triplet logic ---------------------------
__global__ __launch_bounds__(256) void row_kernel(
    const float* __restrict__ prob, const int* __restrict__ targets,
    const float* __restrict__ thrp)
{
    __shared__ float row[NROW];         // 16 KB
    __shared__ ull warpRed[8];
    __shared__ float s_VA, s_VB, s_IC;
    __shared__ int   s_sel[12];

    const int i = blockIdx.x;
    const int tid = threadIdx.x;
    const int lane = tid & 31, wid = tid >> 5;
    const float thr = *thrp;
    const int tgt_i = targets[i];
    const float* drow = g_dist + (size_t)i * NROW;

    {
        const float4* dr4 = (const float4*)drow;
        float4* r4 = (float4*)row;
        for (int t = tid; t < NROW / 4; t += 256) r4[t] = dr4[t];
    }
    __syncthreads();

    // block max over ull: warp shuffle + 8-value smem combine (2 syncs)
#define BLOCK_MAX_ULL(v, out) {                                        \
        ull _m = (v);                                                  \
        for (int _o = 16; _o > 0; _o >>= 1) {                          \
            ull _t = __shfl_xor_sync(0xffffffffu, _m, _o);             \
            if (_t > _m) _m = _t;                                      \
        }                                                              \
        if (lane == 0) warpRed[wid] = _m;                              \
        __syncthreads();                                               \
        ull _r = warpRed[0];                                           \
        _Pragma("unroll")                                              \
        for (int _w = 1; _w < 8; _w++) if (warpRed[_w] > _r) _r = warpRed[_w]; \
        __syncthreads();                                               \
        (out) = _r;                                                    \
    }

    ull key[16];

    // ---- IC: stable top-20 (desc) over cols [64,4096), bugged gather row[pos-64]
#pragma unroll
    for (int s = 0; s < 16; s++) {
        int j = 64 + tid + (s << 8);
        key[s] = (j < NROW) ? (((ull)fkey(row[j]) << 12) | (unsigned)(4095 - j)) : 0ull;
    }
    float icsum = 0.f;
    for (int it = 0; it < 20; it++) {
        ull lb = 0;
#pragma unroll
        for (int s = 0; s < 16; s++) if (key[s] > lb) lb = key[s];
        ull win; BLOCK_MAX_ULL(lb, win);
#pragma unroll
        for (int s = 0; s < 16; s++) if (key[s] == win) key[s] = 0;
        if (tid == 0) {
            int pos = 4095 - (int)(win & 0xFFFull);
            icsum += row[pos - 64];
        }
    }
    if (tid == 0) s_IC = icsum * (1.f / 20.f);

    // ---- VA / VB: stable top-20 in 32-wide slices (warps 0,1), bugged gather
    if (wid < 2) {
        int base = wid * 32;
        ull k = ((ull)fkey(row[base + lane]) << 6) | (unsigned)(31 - lane);
        unsigned removed = 0;
        float s = 0.f;
        for (int t = 0; t < 20; t++) {
            ull kk = ((removed >> lane) & 1u) ? 0ull : k;
            for (int o = 16; o > 0; o >>= 1) {
                ull tt = __shfl_xor_sync(0xffffffffu, kk, o);
                if (tt > kk) kk = tt;
            }
            int bq = 31 - (int)(kk & 63ull);
            removed |= 1u << bq;
            s += row[bq];                       // RELATIVE index gather (the bug)
        }
        if (lane == 0) { if (wid == 0) s_VA = s * (1.f / 20.f); else s_VB = s * (1.f / 20.f); }
    }

    // ---- 12 nearest negatives (stable ascending)
#pragma unroll
    for (int s = 0; s < 16; s++) {
        int j = tid + (s << 8);
        bool neg = (targets[j] != tgt_i);
        key[s] = neg ? ((((ull)(~fkey(row[j]))) << 12) | (unsigned)(4095 - j)) : 0ull;
    }
    for (int it = 0; it < 12; it++) {
        ull lb = 0;
#pragma unroll
        for (int s = 0; s < 16; s++) if (key[s] > lb) lb = key[s];
        ull win; BLOCK_MAX_ULL(lb, win);
#pragma unroll
        for (int s = 0; s < 16; s++) if (key[s] == win) key[s] = 0;
        if (tid == 0) s_sel[it] = 4095 - (int)(win & 0xFFFull);
    }

    // ---- gumbel argmax over class members (monotone in folded bits)
    uint2 kg1 = threefry(0u, 42u, 0u, 0u);      // foldlike split of key(42)
    uint2 kg2 = threefry(0u, 42u, 0u, 1u);
    long long b1 = -1, b2c = -1, b2a = -1;
    for (int s = 0; s < 16; s++) {
        int j = tid + (s << 8);
        if (j == i || targets[j] != tgt_i) continue;
        unsigned m = (unsigned)(i * NROW + j);
        unsigned u1 = gbits(kg1, m) >> 9;
        unsigned u2 = gbits(kg2, m) >> 9;
        long long c1 = ((long long)u1 << 12) | (long long)(4095 - j);
        long long c2 = ((long long)u2 << 12) | (long long)(4095 - j);
        if (c1 > b1) b1 = c1;
        if (c2 > b2a) b2a = c2;
        if (prob[j] >= thr && c2 > b2c) b2c = c2;
    }
    ull R1u, R2cu, R2au;
    BLOCK_MAX_ULL((ull)(b1 + 1),  R1u);
    BLOCK_MAX_ULL((ull)(b2c + 1), R2cu);
    BLOCK_MAX_ULL((ull)(b2a + 1), R2au);
    long long R1 = (long long)R1u - 1, R2c = (long long)R2cu - 1, R2a = (long long)R2au - 1;
    int p_idx = (R1 >= 0) ? (4095 - (int)(R1 & 0xFFF)) : i;
    int p_new = (R2c >= 0) ? (4095 - (int)(R2c & 0xFFF))
               : ((R2a >= 0) ? (4095 - (int)(R2a & 0xFFF)) : i);

    // ---- final per-row triplet logic (thread 0)
    if (tid == 0) {
        const float margin = 0.3f;
        int hn = s_sel[0];
        int first = 10;
        for (int t = 0; t < 10; t++) {
            if (prob[s_sel[1 + t]] >= thr) { first = t; break; }
        }
        int hn_new = s_sel[1 + first];

        float d_ip      = row[p_idx];
        float d_ihn     = row[hn];
        float d_ihn_new = row[hn_new];
        float d_ipnew   = row[p_new];
        bool conf_p  = prob[p_idx] >= thr;
        bool conf_hn = prob[hn]    >= thr;
        bool FN = (g_predArg[hn] == tgt_i);

        float ap = d_ip, an = d_ihn;
        bool bFN = conf_p && !conf_hn && FN;
        if (bFN) { ap = (d_ip + d_ihn) * 0.5f; an = d_ihn_new; }
        bool cRes = (!conf_p && conf_hn) || (!conf_p && !conf_hn && !FN);
        if (cRes) { an = (d_ip + d_ihn) * 0.5f; ap = d_ipnew; }
        bool inv = !conf_p && !conf_hn && FN;
        float c_conf = inv ? fmaxf(an - ap + margin, 0.f)
                           : fmaxf(ap - an + margin, 0.f);

        float apA = row[min(i + 32, NROW - 1)];
        float apB = row[max(i - 32, 0)];
        float apC = row[i];
        float cA = (fmaxf(apA - s_IC + margin, 0.f) + fmaxf(apA - s_VA + margin, 0.f)) * 0.5f;
        float cB = (fmaxf(apB - s_IC + margin, 0.f) + fmaxf(apB - s_VB + margin, 0.f)) * 0.5f;
        float cC = fmaxf(apC - s_IC + margin, 0.f);
        float c_unconf = (i < 32) ? cA : ((i < 64) ? cB : cC);

        bool confident_i = prob[i] >= thr;
        float c = confident_i ? c_conf : c_unconf;
        g_c[i] = c;
        g_flag[i] = (confident_i && (an >= ap)) ? 1 : 0;
    }
}

// ---------------- deterministic final reduction -------------------------------
__global__ __launch_bounds__(256) void final_kernel(
    const float* __restrict__ prob, const float* __restrict__ thrp,
    float* __restrict__ out, int out_size)
{
    __shared__ float sred[256];
    __shared__ int   ired[256], ired2[256];
    __shared__ int   s_j;
    int tid = threadIdx.x;
    float thr = *thrp;

    if (tid == 0) {
        int j = -1;
        for (int r = 0; r < 64; r++) if (!(prob[r] >= thr)) j = r;
        s_j = j;
    }
    __syncthreads();
    int j = s_j;

    float ls = 0.f; int cor = 0, cnt = 0;
    for (int r = tid; r < NROW; r += 256) {
        bool conf = prob[r] >= thr;
        bool ovr = (!conf) && (r < 64);
        bool keep = (r > j) && !ovr;
        if (keep) ls += g_c[r];
        if (conf) { cnt++; cor += g_flag[r]; }
    }
    sred[tid] = ls; ired[tid] = cor; ired2[tid] = cnt;
    __syncthreads();
    for (int s = 128; s > 0; s >>= 1) {
        if (tid < s) {
            sred[tid] += sred[tid + s];
            ired[tid] += ired[tid + s];
            ired2[tid] += ired2[tid + s];
        }
        __syncthreads();
    }
    if (tid == 0) {
        float loss = sred[0] + ((j >= 0) ? g_c[j] : 0.f);
        out[0] = loss * (1.f / (float)NROW);
        if (out_size > 1) out[1] = (float)ired[0];
        if (out_size > 2) out[2] = (float)ired2[0];
    }
    for (int t = 3 + tid; t < out_size; t += 256) out[t] = 0.f;
}

// ---------------- launch ------------------------------------------------------
extern "C" void kernel_launch(void* const* d_in, const int* in_sizes, int n_in,
                              void* d_out, int out_size) {
    const float* X       = (const float*)d_in[0];   // inputs (4096,1024) f32
    const float* P       = (const float*)d_in[1];   // prediction (4096,64) f32
    const int*   targets = (const int*)  d_in[2];   // targets (4096) i32
    const float* prob    = (const float*)d_in[4];   // prob (4096) f32
    const float* thr     = (const float*)d_in[5];   // threshold (1) f32
    float* out = (float*)d_out;

    sq_kernel<<<512, 256>>>(X);
    predarg_kernel<<<16, 256>>>(P);
    split_kernel<<<1024, 256>>>(X);
    dim3 g(NROW / 128, NROW / 128);
    gemm_bf16<<<g, 256>>>();
    row_kernel<<<NROW, 256>>>(prob, targets, thr);
    final_kernel<<<1, 256>>>(prob, thr, out, out_size);
}

// round 11
// speedup vs baseline: 2.6657x; 1.0783x over previous
#include <cuda_runtime.h>
#include <cuda_bf16.h>

#define NROW 4096
#define DIM  1024

// ---------------- scratch (device globals; no allocation allowed) -------------
__device__ float g_dist[NROW * NROW];            // 64 MB distance matrix
__device__ __nv_bfloat16 g_Ah[NROW * DIM];       // 8 MB hi split
__device__ __nv_bfloat16 g_Al[NROW * DIM];       // 8 MB lo split
__device__ float g_sq[NROW];
__device__ int   g_predArg[NROW];
__device__ float g_c[NROW];
__device__ int   g_flag[NROW];

#define FPINF __int_as_float(0x7f800000)
typedef unsigned long long ull;

// ---------------- threefry2x32 (bit-exact vs JAX partitionable) ---------------
__device__ __forceinline__ unsigned rotl32(unsigned v, int r) {
    return (v << r) | (v >> (32 - r));
}

__device__ __forceinline__ uint2 threefry(unsigned k0, unsigned k1,
                                          unsigned x0, unsigned x1) {
    unsigned ks2 = k0 ^ k1 ^ 0x1BD11BDAu;
    x0 += k0; x1 += k1;
#define TFR(R) { x0 += x1; x1 = rotl32(x1, R); x1 ^= x0; }
    TFR(13) TFR(15) TFR(26) TFR(6)   x0 += k1;  x1 += ks2 + 1u;
    TFR(17) TFR(29) TFR(16) TFR(24)  x0 += ks2; x1 += k0  + 2u;
    TFR(13) TFR(15) TFR(26) TFR(6)   x0 += k0;  x1 += k1  + 3u;
    TFR(17) TFR(29) TFR(16) TFR(24)  x0 += k1;  x1 += ks2 + 4u;
    TFR(13) TFR(15) TFR(26) TFR(6)   x0 += ks2; x1 += k0  + 5u;
#undef TFR
    return make_uint2(x0, x1);
}

__device__ __forceinline__ unsigned gbits(uint2 key, unsigned m) {
    uint2 r = threefry(key.x, key.y, 0u, m);
    return r.x ^ r.y;
}

// order-preserving float -> uint key (no NaNs present)
__device__ __forceinline__ unsigned fkey(float f) {
    unsigned b = __float_as_uint(f);
    return (b & 0x80000000u) ? ~b : (b | 0x80000000u);
}

__device__ __forceinline__ ull warpMaxU64(ull x) {
#pragma unroll
    for (int o = 16; o > 0; o >>= 1) {
        ull t = __shfl_xor_sync(0xffffffffu, x, o);
        if (t > x) x = t;
    }
    return x;
}

// ---------------- small prep kernels -----------------------------------------
__global__ void sq_kernel(const float* __restrict__ X) {
    int warp = (blockIdx.x * blockDim.x + threadIdx.x) >> 5;
    int lane = threadIdx.x & 31;
    if (warp >= NROW) return;
    const float* xr = X + (size_t)warp * DIM;
    float s = 0.f;
    for (int k = lane; k < DIM; k += 32) { float v = xr[k]; s = fmaf(v, v, s); }
    for (int o = 16; o > 0; o >>= 1) s += __shfl_xor_sync(0xffffffffu, s, o);
    if (lane == 0) g_sq[warp] = s;
}

__global__ void predarg_kernel(const float* __restrict__ P) {
    int i = blockIdx.x * blockDim.x + threadIdx.x;
    if (i >= NROW) return;
    const float* pr = P + (size_t)i * 64;
    float bv = pr[0]; int bi = 0;
    for (int k = 1; k < 64; k++) { float v = pr[k]; if (v > bv) { bv = v; bi = k; } }
    g_predArg[i] = bi;
}

__global__ void split_kernel(const float* __restrict__ X) {
    int idx = blockIdx.x * blockDim.x + threadIdx.x;
    const float2* x2 = (const float2*)X;
    __nv_bfloat162* ah2 = (__nv_bfloat162*)g_Ah;
    __nv_bfloat162* al2 = (__nv_bfloat162*)g_Al;
    for (int t = idx; t < NROW * DIM / 2; t += gridDim.x * blockDim.x) {
        float2 v = x2[t];
        __nv_bfloat16 h0 = __float2bfloat16(v.x);
        __nv_bfloat16 h1 = __float2bfloat16(v.y);
        __nv_bfloat16 l0 = __float2bfloat16(v.x - __bfloat162float(h0));
        __nv_bfloat16 l1 = __float2bfloat16(v.y - __bfloat162float(h1));
        ah2[t] = __halves2bfloat162(h0, h1);
        al2[t] = __halves2bfloat162(l0, l1);
    }
}

// ---------------- tensor-core split-bf16 GEMM -> dist -------------------------
__device__ __forceinline__ void ldsm_x4(unsigned& r0, unsigned& r1,
                                        unsigned& r2, unsigned& r3, unsigned a) {
    asm volatile("ldmatrix.sync.aligned.m8n8.x4.shared.b16 {%0,%1,%2,%3}, [%4];"
                 : "=r"(r0), "=r"(r1), "=r"(r2), "=r"(r3) : "r"(a));
}
__device__ __forceinline__ void mma_bf16(float* d, const unsigned* a,
                                         unsigned b0, unsigned b1) {
    asm volatile(
        "mma.sync.aligned.m16n8k16.row.col.f32.bf16.bf16.f32 "
        "{%0,%1,%2,%3}, {%4,%5,%6,%7}, {%8,%9}, {%0,%1,%2,%3};"
        : "+f"(d[0]), "+f"(d[1]), "+f"(d[2]), "+f"(d[3])
        : "r"(a[0]), "r"(a[1]), "r"(a[2]), "r"(a[3]), "r"(b0), "r"(b1));
}
__device__ __forceinline__ void cp16(unsigned dst, const void* src) {
    asm volatile("cp.async.cg.shared.global [%0], [%1], 16;" :: "r"(dst), "l"(src));
}

// swizzled byte offset of (row, 16B-half) within a 128x32B tile
__device__ __forceinline__ unsigned sw_off(int row, int half) {
    return (unsigned)(row * 32 + (((half ^ (row >> 2)) & 1) << 4));
}
#define TOFF(s, t) (((s) * 4 + (t)) * 128 * 32)

__global__ __launch_bounds__(256, 2) void gemm_bf16() {
    __shared__ __align__(16) unsigned char smem[3 * 4 * 128 * 32]; // 48 KB exactly

    if (blockIdx.x < blockIdx.y) return;   // symmetry: upper blocks only
    const int bi = blockIdx.y * 128;
    const int bj = blockIdx.x * 128;
    const int tid = threadIdx.x;
    const int lane = tid & 31, wid = tid >> 5;
    const int wm = wid >> 2, wn = wid & 3;  // warp tile: 64(m) x 32(n)

    unsigned sbase = (unsigned)__cvta_generic_to_shared(smem);

    float acc[4][4][4];
#pragma unroll
    for (int a = 0; a < 4; a++)
#pragma unroll
        for (int b = 0; b < 4; b++)
#pragma unroll
            for (int c = 0; c < 4; c++) acc[a][b][c] = 0.f;

    const int lrow = tid >> 1, lhalf = tid & 1;   // loader mapping
    const __nv_bfloat16* srcA_h = g_Ah + (size_t)(bi + lrow) * DIM + lhalf * 8;
    const __nv_bfloat16* srcA_l = g_Al + (size_t)(bi + lrow) * DIM + lhalf * 8;
    const __nv_bfloat16* srcB_h = g_Ah + (size_t)(bj + lrow) * DIM + lhalf * 8;
    const __nv_bfloat16* srcB_l = g_Al + (size_t)(bj + lrow) * DIM + lhalf * 8;
    unsigned dsw = sw_off(lrow, lhalf);

#define LOAD_STAGE(k0, s) {                                   \
        cp16(sbase + TOFF(s, 0) + dsw, srcA_h + (k0));        \
        cp16(sbase + TOFF(s, 1) + dsw, srcA_l + (k0));        \
        cp16(sbase + TOFF(s, 2) + dsw, srcB_h + (k0));        \
        cp16(sbase + TOFF(s, 3) + dsw, srcB_l + (k0));        \
    }

    const int a_r = (lane & 7) + ((lane >> 3) & 1) * 8;
    const int a_h = (lane >> 4) & 1;
    const int b_mat = lane >> 3;
    const int b_n = ((b_mat >> 1) & 1) * 8 + (lane & 7);
    const int b_h = b_mat & 1;

    LOAD_STAGE(0, 0);
    asm volatile("cp.async.commit_group;");
    LOAD_STAGE(16, 1);
    asm volatile("cp.async.commit_group;");

    int cur = 0;
    for (int ks = 0; ks < 64; ks++) {
        __syncthreads();                    // all warps done with the slot we refill
        if (ks < 62) {
            int nxt = cur + 2; if (nxt >= 3) nxt -= 3;
            LOAD_STAGE((ks + 2) * 16, nxt);
        }
        asm volatile("cp.async.commit_group;");
        asm volatile("cp.async.wait_group 2;");   // stage `cur` (ks) is ready

        unsigned ah[4][4], bb[2][4];
#pragma unroll
        for (int mt = 0; mt < 4; mt++) {
            int r = wm * 64 + mt * 16 + a_r;
            ldsm_x4(ah[mt][0], ah[mt][1], ah[mt][2], ah[mt][3],
                    sbase + TOFF(cur, 0) + sw_off(r, a_h));
        }
#pragma unroll
        for (int p = 0; p < 2; p++) {
            int n = wn * 32 + p * 16 + b_n;
            ldsm_x4(bb[p][0], bb[p][1], bb[p][2], bb[p][3],
                    sbase + TOFF(cur, 2) + sw_off(n, b_h));
        }
        // hi*hi
#pragma unroll
        for (int mt = 0; mt < 4; mt++)
#pragma unroll
            for (int nt = 0; nt < 4; nt++)
                mma_bf16(acc[mt][nt], ah[mt], bb[nt >> 1][(nt & 1) * 2],
                         bb[nt >> 1][(nt & 1) * 2 + 1]);
        // lo*hi
        {
            unsigned al[4][4];
#pragma unroll
            for (int mt = 0; mt < 4; mt++) {
                int r = wm * 64 + mt * 16 + a_r;
                ldsm_x4(al[mt][0], al[mt][1], al[mt][2], al[mt][3],
                        sbase + TOFF(cur, 1) + sw_off(r, a_h));
            }
#pragma unroll
            for (int mt = 0; mt < 4; mt++)
#pragma unroll
                for (int nt = 0; nt < 4; nt++)
                    mma_bf16(acc[mt][nt], al[mt], bb[nt >> 1][(nt & 1) * 2],
                             bb[nt >> 1][(nt & 1) * 2 + 1]);
        }
        // hi*lo
#pragma unroll
        for (int p = 0; p < 2; p++) {
            int n = wn * 32 + p * 16 + b_n;
            ldsm_x4(bb[p][0], bb[p][1], bb[p][2], bb[p][3],
                    sbase + TOFF(cur, 3) + sw_off(n, b_h));
        }
#pragma unroll
        for (int mt = 0; mt < 4; mt++)
#pragma unroll
            for (int nt = 0; nt < 4; nt++)
                mma_bf16(acc[mt][nt], ah[mt], bb[nt >> 1][(nt & 1) * 2],
                         bb[nt >> 1][(nt & 1) * 2 + 1]);

        cur++; if (cur >= 3) cur = 0;
    }

    // epilogue: d2 -> sqrt -> store direct + mirror (g_sq read via L2; 16 KB resident)
    const bool diag = (blockIdx.x == blockIdx.y);
    const int r_b = wm * 64 + (lane >> 2);
    const int c_b = wn * 32 + (lane & 3) * 2;
#pragma unroll
    for (int mt = 0; mt < 4; mt++) {
#pragma unroll
        for (int h = 0; h < 2; h++) {
            int r = r_b + mt * 16 + h * 8;
            int ii = bi + r;
            float sqi = g_sq[ii];
#pragma unroll
            for (int nt = 0; nt < 4; nt++) {
                int c = c_b + nt * 8;
                int jj = bj + c;
                float v0 = sqrtf(fmaxf(sqi + g_sq[jj]     - 2.f * acc[mt][nt][2 * h],     1e-12f));
                float v1 = sqrtf(fmaxf(sqi + g_sq[jj + 1] - 2.f * acc[mt][nt][2 * h + 1], 1e-12f));
                float2 o; o.x = v0; o.y = v1;
                *reinterpret_cast<float2*>(&g_dist[(size_t)ii * NROW + jj]) = o;
                if (!diag) {
                    g_dist[(size_t)jj * NROW + ii] = v0;
                    g_dist[(size_t)(jj + 1) * NROW + ii] = v1;
                }
            }
        }
    }
}

// ---------------- per-row selection + triplet logic ---------------------------
// 512 threads = 16 warps. Warp-local top-k (no barriers) + single-warp merge.
__global__ __launch_bounds__(512) void row_kernel(
    const float* __restrict__ prob, const int* __restrict__ targets,
    const float* __restrict__ thrp)
{
    __shared__ float row[NROW];          // 16 KB
    __shared__ int   stgt[NROW];         // 16 KB
    __shared__ ull   icList[16][20];
    __shared__ ull   ngList[16][12];
    __shared__ ull   gRed[16][3];
    __shared__ ull   s_g[3];
    __shared__ float s_VA, s_VB, s_IC;
    __shared__ int   s_sel[12];

    const int i = blockIdx.x;
    const int tid = threadIdx.x;
    const int lane = tid & 31, wid = tid >> 5;
    const float thr = *thrp;
    const float* drow = g_dist + (size_t)i * NROW;

    for (int t = tid; t < NROW / 4; t += 512) {
        ((float4*)row)[t] = ((const float4*)drow)[t];
        ((int4*)stgt)[t]  = ((const int4*)targets)[t];
    }
    __syncthreads();
    const int tgt_i = stgt[i];

    ull k[8];

    // ---- IC: stable top-20 (desc) over cols [64,4096), bugged gather row[pos-64]
#pragma unroll
    for (int s = 0; s < 8; s++) {
        int j = 64 + tid + (s << 9);
        k[s] = (j < NROW) ? (((ull)fkey(row[j]) << 12) | (unsigned)(4095 - j)) : 0ull;
    }
    for (int it = 0; it < 20; it++) {
        ull lb = k[0];
#pragma unroll
        for (int s = 1; s < 8; s++) if (k[s] > lb) lb = k[s];
        ull win = warpMaxU64(lb);
#pragma unroll
        for (int s = 0; s < 8; s++) if (k[s] == win) k[s] = 0;
        if (lane == 0) icList[wid][it] = win;
    }
    __syncthreads();

    // merge on warp 0; VA on warp 14; VB on warp 15 (concurrent)
    if (wid == 0) {
        ull cur = (lane < 16) ? icList[lane][0] : 0;
        int hp = 1;
        float icsum = 0.f;
        for (int it = 0; it < 20; it++) {
            ull win = warpMaxU64(cur);
            if (cur == win && lane < 16) { cur = (hp < 20) ? icList[lane][hp] : 0; hp++; }
            if (lane == 0) {
                int pos = 4095 - (int)(win & 0xFFFull);
                icsum += row[pos - 64];
            }
        }
        if (lane == 0) s_IC = icsum * (1.f / 20.f);
    } else if (wid >= 14) {
        int base = (wid - 14) * 32;
        ull kk0 = ((ull)fkey(row[base + lane]) << 6) | (unsigned)(31 - lane);
        unsigned removed = 0; float s = 0.f;
        for (int t = 0; t < 20; t++) {
            ull kk = ((removed >> lane) & 1u) ? 0ull : kk0;
            kk = warpMaxU64(kk);
            int bq = 31 - (int)(kk & 63ull);
            removed |= 1u << bq;
            s += row[bq];                    // RELATIVE index gather (the bug)
        }
        if (lane == 0) { if (wid == 14) s_VA = s * (1.f / 20.f); else s_VB = s * (1.f / 20.f); }
    }

    // ---- 12 nearest negatives (stable ascending)
#pragma unroll
    for (int s = 0; s < 8; s++) {
        int j = tid + (s << 9);
        k[s] = (stgt[j] != tgt_i)
             ? ((((ull)(~fkey(row[j]))) << 12) | (unsigned)(4095 - j)) : 0ull;
    }
    for (int it = 0; it < 12; it++) {
        ull lb = k[0];
#pragma unroll
        for (int s = 1; s < 8; s++) if (k[s] > lb) lb = k[s];
        ull win = warpMaxU64(lb);
#pragma unroll
        for (int s = 0; s < 8; s++) if (k[s] == win) k[s] = 0;
        if (lane == 0) ngList[wid][it] = win;
    }
    __syncthreads();
    if (wid == 0) {
        ull cur = (lane < 16) ? ngList[lane][0] : 0;
        int hp = 1;
        for (int it = 0; it < 12; it++) {
            ull win = warpMaxU64(cur);
            if (cur == win && lane < 16) { cur = (hp < 12) ? ngList[lane][hp] : 0; hp++; }
            if (lane == 0) s_sel[it] = 4095 - (int)(win & 0xFFFull);
        }
    }

    // ---- gumbel argmax over class members (monotone in folded bits)
    uint2 kg1 = threefry(0u, 42u, 0u, 0u);
    uint2 kg2 = threefry(0u, 42u, 0u, 1u);
    long long b1 = -1, b2c = -1, b2a = -1;
#pragma unroll
    for (int s = 0; s < 8; s++) {
        int j = tid + (s << 9);
        if (j == i || stgt[j] != tgt_i) continue;
        unsigned m = (unsigned)(i * NROW + j);
        unsigned u1 = gbits(kg1, m) >> 9;
        unsigned u2 = gbits(kg2, m) >> 9;
        long long c1 = ((long long)u1 << 12) | (long long)(4095 - j);
        long long c2 = ((long long)u2 << 12) | (long long)(4095 - j);
        if (c1 > b1) b1 = c1;
        if (c2 > b2a) b2a = c2;
        if (prob[j] >= thr && c2 > b2c) b2c = c2;
    }
    {
        ull v0 = warpMaxU64((ull)(b1 + 1));
        ull v1 = warpMaxU64((ull)(b2c + 1));
        ull v2 = warpMaxU64((ull)(b2a + 1));
        if (lane == 0) { gRed[wid][0] = v0; gRed[wid][1] = v1; gRed[wid][2] = v2; }
    }
    __syncthreads();
    if (wid == 0) {
        ull a0 = (lane < 16) ? gRed[lane][0] : 0;
        ull a1 = (lane < 16) ? gRed[lane][1] : 0;
        ull a2 = (lane < 16) ? gRed[lane][2] : 0;
        a0 = warpMaxU64(a0); a1 = warpMaxU64(a1); a2 = warpMaxU64(a2);
        if (lane == 0) { s_g[0] = a0; s_g[1] = a1; s_g[2] = a2; }
    }
    __syncthreads();

    // ---- final per-row triplet logic (thread 0)
    if (tid == 0) {
        long long R1 = (long long)s_g[0] - 1;
        long long R2c = (long long)s_g[1] - 1;
        long long R2a = (long long)s_g[2] - 1;
        int p_idx = (R1 >= 0) ? (4095 - (int)(R1 & 0xFFF)) : i;
        int p_new = (R2c >= 0) ? (4095 - (int)(R2c & 0xFFF))
                   : ((R2a >= 0) ? (4095 - (int)(R2a & 0xFFF)) : i);

        const float margin = 0.3f;
        int hn = s_sel[0];
        int first = 10;
        for (int t = 0; t < 10; t++) {
            if (prob[s_sel[1 + t]] >= thr) { first = t; break; }
        }
        int hn_new = s_sel[1 + first];

        float d_ip      = row[p_idx];
        float d_ihn     = row[hn];
        float d_ihn_new = row[hn_new];
        float d_ipnew   = row[p_new];
        bool conf_p  = prob[p_idx] >= thr;
        bool conf_hn = prob[hn]    >= thr;
        bool FN = (g_predArg[hn] == tgt_i);

        float ap = d_ip, an = d_ihn;
        bool bFN = conf_p && !conf_hn && FN;
        if (bFN) { ap = (d_ip + d_ihn) * 0.5f; an = d_ihn_new; }
        bool cRes = (!conf_p && conf_hn) || (!conf_p && !conf_hn && !FN);
        if (cRes) { an = (d_ip + d_ihn) * 0.5f; ap = d_ipnew; }
        bool inv = !conf_p && !conf_hn && FN;
        float c_conf = inv ? fmaxf(an - ap + margin, 0.f)
                           : fmaxf(ap - an + margin, 0.f);

        float apA = row[min(i + 32, NROW - 1)];
        float apB = row[max(i - 32, 0)];
        float apC = row[i];
        float cA = (fmaxf(apA - s_IC + margin, 0.f) + fmaxf(apA - s_VA + margin, 0.f)) * 0.5f;
        float cB = (fmaxf(apB - s_IC + margin, 0.f) + fmaxf(apB - s_VB + margin, 0.f)) * 0.5f;
        float cC = fmaxf(apC - s_IC + margin, 0.f);
        float c_unconf = (i < 32) ? cA : ((i < 64) ? cB : cC);

        bool confident_i = prob[i] >= thr;
        float c = confident_i ? c_conf : c_unconf;
        g_c[i] = c;
        g_flag[i] = (confident_i && (an >= ap)) ? 1 : 0;
    }
}

// ---------------- deterministic final reduction -------------------------------
__global__ __launch_bounds__(256) void final_kernel(
    const float* __restrict__ prob, const float* __restrict__ thrp,
    float* __restrict__ out, int out_size)
{
    __shared__ float sred[256];
    __shared__ int   ired[256], ired2[256];
    __shared__ int   s_j;
    int tid = threadIdx.x;
    float thr = *thrp;

    if (tid == 0) {
        int j = -1;
        for (int r = 0; r < 64; r++) if (!(prob[r] >= thr)) j = r;
        s_j = j;
    }
    __syncthreads();
    int j = s_j;

    float ls = 0.f; int cor = 0, cnt = 0;
    for (int r = tid; r < NROW; r += 256) {
        bool conf = prob[r] >= thr;
        bool ovr = (!conf) && (r < 64);
        bool keep = (r > j) && !ovr;
        if (keep) ls += g_c[r];
        if (conf) { cnt++; cor += g_flag[r]; }
    }
    sred[tid] = ls; ired[tid] = cor; ired2[tid] = cnt;
    __syncthreads();
    for (int s = 128; s > 0; s >>= 1) {
        if (tid < s) {
            sred[tid] += sred[tid + s];
            ired[tid] += ired[tid + s];
            ired2[tid] += ired2[tid + s];
        }
        __syncthreads();
    }
    if (tid == 0) {
        float loss = sred[0] + ((j >= 0) ? g_c[j] : 0.f);
        out[0] = loss * (1.f / (float)NROW);
        if (out_size > 1) out[1] = (float)ired[0];
        if (out_size > 2) out[2] = (float)ired2[0];
    }
    for (int t = 3 + tid; t < out_size; t += 256) out[t] = 0.f;
}

// ---------------- launch ------------------------------------------------------
extern "C" void kernel_launch(void* const* d_in, const int* in_sizes, int n_in,
                              void* d_out, int out_size) {
    const float* X       = (const float*)d_in[0];   // inputs (4096,1024) f32
    const float* P       = (const float*)d_in[1];   // prediction (4096,64) f32
    const int*   targets = (const int*)  d_in[2];   // targets (4096) i32
    const float* prob    = (const float*)d_in[4];   // prob (4096) f32
    const float* thr     = (const float*)d_in[5];   // threshold (1) f32
    float* out = (float*)d_out;

    sq_kernel<<<512, 256>>>(X);
    predarg_kernel<<<16, 256>>>(P);
    split_kernel<<<1024, 256>>>(X);
    dim3 g(NROW / 128, NROW / 128);
    gemm_bf16<<<g, 256>>>();
    row_kernel<<<NROW, 512>>>(prob, targets, thr);
    final_kernel<<<1, 256>>>(prob, thr, out, out_size);
}

// round 12
// speedup vs baseline: 3.8731x; 1.4530x over previous
#include <cuda_runtime.h>
#include <cuda_bf16.h>

#define NROW 4096
#define DIM  1024

// ---------------- scratch (device globals; no allocation allowed) -------------
__device__ float g_dist[NROW * NROW];            // 64 MB distance matrix
__device__ __nv_bfloat16 g_Ah[NROW * DIM];       // 8 MB hi split
__device__ __nv_bfloat16 g_Al[NROW * DIM];       // 8 MB lo split
__device__ float g_sq[NROW];
__device__ int   g_predArg[NROW];
__device__ float g_c[NROW];
__device__ int   g_flag[NROW];

typedef unsigned long long ull;

// ---------------- threefry2x32 (bit-exact vs JAX partitionable) ---------------
__device__ __forceinline__ unsigned rotl32(unsigned v, int r) {
    return (v << r) | (v >> (32 - r));
}

__device__ __forceinline__ uint2 threefry(unsigned k0, unsigned k1,
                                          unsigned x0, unsigned x1) {
    unsigned ks2 = k0 ^ k1 ^ 0x1BD11BDAu;
    x0 += k0; x1 += k1;
#define TFR(R) { x0 += x1; x1 = rotl32(x1, R); x1 ^= x0; }
    TFR(13) TFR(15) TFR(26) TFR(6)   x0 += k1;  x1 += ks2 + 1u;
    TFR(17) TFR(29) TFR(16) TFR(24)  x0 += ks2; x1 += k0  + 2u;
    TFR(13) TFR(15) TFR(26) TFR(6)   x0 += k0;  x1 += k1  + 3u;
    TFR(17) TFR(29) TFR(16) TFR(24)  x0 += k1;  x1 += ks2 + 4u;
    TFR(13) TFR(15) TFR(26) TFR(6)   x0 += ks2; x1 += k0  + 5u;
#undef TFR
    return make_uint2(x0, x1);
}

__device__ __forceinline__ unsigned gbits(uint2 key, unsigned m) {
    uint2 r = threefry(key.x, key.y, 0u, m);
    return r.x ^ r.y;
}

__device__ __forceinline__ ull warpMaxU64(ull x) {
#pragma unroll
    for (int o = 16; o > 0; o >>= 1) {
        ull t = __shfl_xor_sync(0xffffffffu, x, o);
        if (t > x) x = t;
    }
    return x;
}

// ---------------- small prep kernels -----------------------------------------
__global__ void sq_kernel(const float* __restrict__ X) {
    int warp = (blockIdx.x * blockDim.x + threadIdx.x) >> 5;
    int lane = threadIdx.x & 31;
    if (warp >= NROW) return;
    const float* xr = X + (size_t)warp * DIM;
    float s = 0.f;
    for (int k = lane; k < DIM; k += 32) { float v = xr[k]; s = fmaf(v, v, s); }
    for (int o = 16; o > 0; o >>= 1) s += __shfl_xor_sync(0xffffffffu, s, o);
    if (lane == 0) g_sq[warp] = s;
}

__global__ void predarg_kernel(const float* __restrict__ P) {
    int i = blockIdx.x * blockDim.x + threadIdx.x;
    if (i >= NROW) return;
    const float* pr = P + (size_t)i * 64;
    float bv = pr[0]; int bi = 0;
    for (int k = 1; k < 64; k++) { float v = pr[k]; if (v > bv) { bv = v; bi = k; } }
    g_predArg[i] = bi;
}

__global__ void split_kernel(const float* __restrict__ X) {
    int idx = blockIdx.x * blockDim.x + threadIdx.x;
    const float2* x2 = (const float2*)X;
    __nv_bfloat162* ah2 = (__nv_bfloat162*)g_Ah;
    __nv_bfloat162* al2 = (__nv_bfloat162*)g_Al;
    for (int t = idx; t < NROW * DIM / 2; t += gridDim.x * blockDim.x) {
        float2 v = x2[t];
        __nv_bfloat16 h0 = __float2bfloat16(v.x);
        __nv_bfloat16 h1 = __float2bfloat16(v.y);
        __nv_bfloat16 l0 = __float2bfloat16(v.x - __bfloat162float(h0));
        __nv_bfloat16 l1 = __float2bfloat16(v.y - __bfloat162float(h1));
        ah2[t] = __halves2bfloat162(h0, h1);
        al2[t] = __halves2bfloat162(l0, l1);
    }
}

// ---------------- tensor-core split-bf16 GEMM -> dist -------------------------
__device__ __forceinline__ void ldsm_x4(unsigned& r0, unsigned& r1,
                                        unsigned& r2, unsigned& r3, unsigned a) {
    asm volatile("ldmatrix.sync.aligned.m8n8.x4.shared.b16 {%0,%1,%2,%3}, [%4];"
                 : "=r"(r0), "=r"(r1), "=r"(r2), "=r"(r3) : "r"(a));
}
__device__ __forceinline__ void mma_bf16(float* d, const unsigned* a,
                                         unsigned b0, unsigned b1) {
    asm volatile(
        "mma.sync.aligned.m16n8k16.row.col.f32.bf16.bf16.f32 "
        "{%0,%1,%2,%3}, {%4,%5,%6,%7}, {%8,%9}, {%0,%1,%2,%3};"
        : "+f"(d[0]), "+f"(d[1]), "+f"(d[2]), "+f"(d[3])
        : "r"(a[0]), "r"(a[1]), "r"(a[2]), "r"(a[3]), "r"(b0), "r"(b1));
}
__device__ __forceinline__ void cp16(unsigned dst, const void* src) {
    asm volatile("cp.async.cg.shared.global [%0], [%1], 16;" :: "r"(dst), "l"(src));
}

// swizzled byte offset of (row, 16B-half) within a 128x32B tile
__device__ __forceinline__ unsigned sw_off(int row, int half) {
    return (unsigned)(row * 32 + (((half ^ (row >> 2)) & 1) << 4));
}
#define TOFF(s, t) (((s) * 4 + (t)) * 128 * 32)

__global__ __launch_bounds__(256, 2) void gemm_bf16() {
    __shared__ __align__(16) unsigned char smem[3 * 4 * 128 * 32]; // 48 KB exactly

    if (blockIdx.x < blockIdx.y) return;   // symmetry: upper blocks only
    const int bi = blockIdx.y * 128;
    const int bj = blockIdx.x * 128;
    const int tid = threadIdx.x;
    const int lane = tid & 31, wid = tid >> 5;
    const int wm = wid >> 2, wn = wid & 3;  // warp tile: 64(m) x 32(n)

    unsigned sbase = (unsigned)__cvta_generic_to_shared(smem);

    float acc[4][4][4];
#pragma unroll
    for (int a = 0; a < 4; a++)
#pragma unroll
        for (int b = 0; b < 4; b++)
#pragma unroll
            for (int c = 0; c < 4; c++) acc[a][b][c] = 0.f;

    const int lrow = tid >> 1, lhalf = tid & 1;   // loader mapping
    const __nv_bfloat16* srcA_h = g_Ah + (size_t)(bi + lrow) * DIM + lhalf * 8;
    const __nv_bfloat16* srcA_l = g_Al + (size_t)(bi + lrow) * DIM + lhalf * 8;
    const __nv_bfloat16* srcB_h = g_Ah + (size_t)(bj + lrow) * DIM + lhalf * 8;
    const __nv_bfloat16* srcB_l = g_Al + (size_t)(bj + lrow) * DIM + lhalf * 8;
    unsigned dsw = sw_off(lrow, lhalf);

#define LOAD_STAGE(k0, s) {                                   \
        cp16(sbase + TOFF(s, 0) + dsw, srcA_h + (k0));        \
        cp16(sbase + TOFF(s, 1) + dsw, srcA_l + (k0));        \
        cp16(sbase + TOFF(s, 2) + dsw, srcB_h + (k0));        \
        cp16(sbase + TOFF(s, 3) + dsw, srcB_l + (k0));        \
    }

    const int a_r = (lane & 7) + ((lane >> 3) & 1) * 8;
    const int a_h = (lane >> 4) & 1;
    const int b_mat = lane >> 3;
    const int b_n = ((b_mat >> 1) & 1) * 8 + (lane & 7);
    const int b_h = b_mat & 1;

    LOAD_STAGE(0, 0);
    asm volatile("cp.async.commit_group;");
    LOAD_STAGE(16, 1);
    asm volatile("cp.async.commit_group;");

    int cur = 0;
    for (int ks = 0; ks < 64; ks++) {
        __syncthreads();                    // all warps done with the slot we refill
        if (ks < 62) {
            int nxt = cur + 2; if (nxt >= 3) nxt -= 3;
            LOAD_STAGE((ks + 2) * 16, nxt);
        }
        asm volatile("cp.async.commit_group;");
        asm volatile("cp.async.wait_group 2;");   // stage `cur` (ks) is ready

        unsigned ah[4][4], bb[2][4];
#pragma unroll
        for (int mt = 0; mt < 4; mt++) {
            int r = wm * 64 + mt * 16 + a_r;
            ldsm_x4(ah[mt][0], ah[mt][1], ah[mt][2], ah[mt][3],
                    sbase + TOFF(cur, 0) + sw_off(r, a_h));
        }
#pragma unroll
        for (int p = 0; p < 2; p++) {
            int n = wn * 32 + p * 16 + b_n;
            ldsm_x4(bb[p][0], bb[p][1], bb[p][2], bb[p][3],
                    sbase + TOFF(cur, 2) + sw_off(n, b_h));
        }
        // hi*hi
#pragma unroll
        for (int mt = 0; mt < 4; mt++)
#pragma unroll
            for (int nt = 0; nt < 4; nt++)
                mma_bf16(acc[mt][nt], ah[mt], bb[nt >> 1][(nt & 1) * 2],
                         bb[nt >> 1][(nt & 1) * 2 + 1]);
        // lo*hi
        {
            unsigned al[4][4];
#pragma unroll
            for (int mt = 0; mt < 4; mt++) {
                int r = wm * 64 + mt * 16 + a_r;
                ldsm_x4(al[mt][0], al[mt][1], al[mt][2], al[mt][3],
                        sbase + TOFF(cur, 1) + sw_off(r, a_h));
            }
#pragma unroll
            for (int mt = 0; mt < 4; mt++)
#pragma unroll
                for (int nt = 0; nt < 4; nt++)
                    mma_bf16(acc[mt][nt], al[mt], bb[nt >> 1][(nt & 1) * 2],
                             bb[nt >> 1][(nt & 1) * 2 + 1]);
        }
        // hi*lo
#pragma unroll
        for (int p = 0; p < 2; p++) {
            int n = wn * 32 + p * 16 + b_n;
            ldsm_x4(bb[p][0], bb[p][1], bb[p][2], bb[p][3],
                    sbase + TOFF(cur, 3) + sw_off(n, b_h));
        }
#pragma unroll
        for (int mt = 0; mt < 4; mt++)
#pragma unroll
            for (int nt = 0; nt < 4; nt++)
                mma_bf16(acc[mt][nt], ah[mt], bb[nt >> 1][(nt & 1) * 2],
                         bb[nt >> 1][(nt & 1) * 2 + 1]);

        cur++; if (cur >= 3) cur = 0;
    }

    // epilogue: d2 -> sqrt -> store direct + mirror (g_sq read via L2)
    const bool diag = (blockIdx.x == blockIdx.y);
    const int r_b = wm * 64 + (lane >> 2);
    const int c_b = wn * 32 + (lane & 3) * 2;
#pragma unroll
    for (int mt = 0; mt < 4; mt++) {
#pragma unroll
        for (int h = 0; h < 2; h++) {
            int r = r_b + mt * 16 + h * 8;
            int ii = bi + r;
            float sqi = g_sq[ii];
#pragma unroll
            for (int nt = 0; nt < 4; nt++) {
                int c = c_b + nt * 8;
                int jj = bj + c;
                float v0 = sqrtf(fmaxf(sqi + g_sq[jj]     - 2.f * acc[mt][nt][2 * h],     1e-12f));
                float v1 = sqrtf(fmaxf(sqi + g_sq[jj + 1] - 2.f * acc[mt][nt][2 * h + 1], 1e-12f));
                float2 o; o.x = v0; o.y = v1;
                *reinterpret_cast<float2*>(&g_dist[(size_t)ii * NROW + jj]) = o;
                if (!diag) {
                    g_dist[(size_t)jj * NROW + ii] = v0;
                    g_dist[(size_t)(jj + 1) * NROW + ii] = v1;
                }
            }
        }
    }
}

// ---------------- per-row selection + triplet logic ---------------------------
// 512 threads = 16 warps. Per-lane Batcher sort + REDUX 2-stage extraction.
// Keys: dist values are strictly positive floats -> raw IEEE bits are
// order-preserving. key = ((ull)bits << 12) | (4095 - j): value desc, j asc.

// descending compare-exchange: a keeps the larger
#define CX(a, b) { ull _mx = (a) > (b) ? (a) : (b); ull _mn = (a) > (b) ? (b) : (a); (a) = _mx; (b) = _mn; }
// Batcher odd-even mergesort, 8 elements, descending (k0 largest)
#define SORT8(k0,k1,k2,k3,k4,k5,k6,k7) {             \
    CX(k0,k1) CX(k2,k3) CX(k4,k5) CX(k6,k7)          \
    CX(k0,k2) CX(k1,k3) CX(k4,k6) CX(k5,k7)          \
    CX(k1,k2) CX(k5,k6)                              \
    CX(k0,k4) CX(k1,k5) CX(k2,k6) CX(k3,k7)          \
    CX(k2,k4) CX(k3,k5)                              \
    CX(k1,k2) CX(k3,k4) CX(k5,k6)                    \
}

__global__ __launch_bounds__(512) void row_kernel(
    const float* __restrict__ prob, const int* __restrict__ targets,
    const float* __restrict__ thrp)
{
    __shared__ float row[NROW];          // 16 KB
    __shared__ ull   icList[16][20];
    __shared__ ull   ngList[16][12];
    __shared__ ull   gRed[16][3];
    __shared__ ull   s_g[3];
    __shared__ float s_VA, s_VB, s_IC;
    __shared__ int   s_sel[12];

    const int i = blockIdx.x;
    const int tid = threadIdx.x;
    const int lane = tid & 31, wid = tid >> 5;
    const float thr = *thrp;
    const int tgt_i = __ldg(&targets[i]);
    const float* drow = g_dist + (size_t)i * NROW;

    for (int t = tid; t < NROW / 4; t += 512)
        ((float4*)row)[t] = ((const float4*)drow)[t];
    __syncthreads();

    ull k0, k1, k2, k3, k4, k5, k6, k7;

    // ---- IC: stable top-20 (desc) over cols [64,4096), bugged gather row[pos-64]
#define MKIC(kv, s) { int j = 64 + tid + ((s) << 9);                         \
        kv = (j < NROW) ? (((ull)__float_as_uint(row[j]) << 12)              \
                           | (unsigned)(4095 - j)) : 0ull; }
    MKIC(k0,0) MKIC(k1,1) MKIC(k2,2) MKIC(k3,3)
    MKIC(k4,4) MKIC(k5,5) MKIC(k6,6) MKIC(k7,7)
    SORT8(k0,k1,k2,k3,k4,k5,k6,k7)
    for (int it = 0; it < 20; it++) {
        unsigned hi = (unsigned)(k0 >> 12);
        unsigned m  = __reduce_max_sync(0xffffffffu, hi);
        unsigned lo = (hi == m) ? (unsigned)(k0 & 0xFFFull) : 0u;
        unsigned l  = __reduce_max_sync(0xffffffffu, lo);
        ull win = ((ull)m << 12) | l;
        if (lane == 0) icList[wid][it] = win;
        if (k0 == win) { k0=k1; k1=k2; k2=k3; k3=k4; k4=k5; k5=k6; k6=k7; k7=0; }
    }
    __syncthreads();

    // merge on warp 0; VA on warp 14; VB on warp 15 (concurrent)
    if (wid == 0) {
        int hp = 0;
        ull head = (lane < 16) ? icList[lane][0] : 0;
        float icsum = 0.f;
        for (int it = 0; it < 20; it++) {
            unsigned hi = (unsigned)(head >> 12);
            unsigned m  = __reduce_max_sync(0xffffffffu, hi);
            unsigned lo = (hi == m) ? (unsigned)(head & 0xFFFull) : 0u;
            unsigned l  = __reduce_max_sync(0xffffffffu, lo);
            ull win = ((ull)m << 12) | l;
            if (head == win && lane < 16) {
                hp++; head = (hp < 20) ? icList[lane][hp] : 0;
            }
            if (lane == 0) {
                int pos = 4095 - (int)(win & 0xFFFull);
                icsum += row[pos - 64];
            }
        }
        if (lane == 0) s_IC = icsum * (1.f / 20.f);
    } else if (wid >= 14) {
        int base = (wid - 14) * 32;
        ull kk0 = ((ull)__float_as_uint(row[base + lane]) << 6) | (unsigned)(31 - lane);
        unsigned removed = 0; float s = 0.f;
        for (int t = 0; t < 20; t++) {
            ull kk = ((removed >> lane) & 1u) ? 0ull : kk0;
            kk = warpMaxU64(kk);
            int bq = 31 - (int)(kk & 63ull);
            removed |= 1u << bq;
            s += row[bq];                    // RELATIVE index gather (the bug)
        }
        if (lane == 0) { if (wid == 14) s_VA = s * (1.f / 20.f); else s_VB = s * (1.f / 20.f); }
    }

    // ---- 12 nearest negatives (stable ascending): key = ~bits (asc dist)
#define MKNG(kv, s) { int j = tid + ((s) << 9);                              \
        int tj = __ldg(&targets[j]);                                         \
        kv = (tj != tgt_i) ? (((ull)(~__float_as_uint(row[j])) << 12)        \
                              | (unsigned)(4095 - j)) : 0ull; }
    MKNG(k0,0) MKNG(k1,1) MKNG(k2,2) MKNG(k3,3)
    MKNG(k4,4) MKNG(k5,5) MKNG(k6,6) MKNG(k7,7)
    SORT8(k0,k1,k2,k3,k4,k5,k6,k7)
    for (int it = 0; it < 12; it++) {
        unsigned hi = (unsigned)(k0 >> 12);
        unsigned m  = __reduce_max_sync(0xffffffffu, hi);
        unsigned lo = (hi == m) ? (unsigned)(k0 & 0xFFFull) : 0u;
        unsigned l  = __reduce_max_sync(0xffffffffu, lo);
        ull win = ((ull)m << 12) | l;
        if (lane == 0) ngList[wid][it] = win;
        if (k0 == win) { k0=k1; k1=k2; k2=k3; k3=k4; k4=k5; k5=k6; k6=k7; k7=0; }
    }
    __syncthreads();
    if (wid == 0) {
        int hp = 0;
        ull head = (lane < 16) ? ngList[lane][0] : 0;
        for (int it = 0; it < 12; it++) {
            unsigned hi = (unsigned)(head >> 12);
            unsigned m  = __reduce_max_sync(0xffffffffu, hi);
            unsigned lo = (hi == m) ? (unsigned)(head & 0xFFFull) : 0u;
            unsigned l  = __reduce_max_sync(0xffffffffu, lo);
            ull win = ((ull)m << 12) | l;
            if (head == win && lane < 16) {
                hp++; head = (hp < 12) ? ngList[lane][hp] : 0;
            }
            if (lane == 0) s_sel[it] = 4095 - (int)(win & 0xFFFull);
        }
    }

    // ---- gumbel argmax over class members (monotone in folded bits)
    uint2 kg1 = threefry(0u, 42u, 0u, 0u);
    uint2 kg2 = threefry(0u, 42u, 0u, 1u);
    long long b1 = -1, b2c = -1, b2a = -1;
#pragma unroll
    for (int s = 0; s < 8; s++) {
        int j = tid + (s << 9);
        if (j == i || __ldg(&targets[j]) != tgt_i) continue;
        unsigned m = (unsigned)(i * NROW + j);
        unsigned u1 = gbits(kg1, m) >> 9;
        unsigned u2 = gbits(kg2, m) >> 9;
        long long c1 = ((long long)u1 << 12) | (long long)(4095 - j);
        long long c2 = ((long long)u2 << 12) | (long long)(4095 - j);
        if (c1 > b1) b1 = c1;
        if (c2 > b2a) b2a = c2;
        if (prob[j] >= thr && c2 > b2c) b2c = c2;
    }
    {
        ull v0 = warpMaxU64((ull)(b1 + 1));
        ull v1 = warpMaxU64((ull)(b2c + 1));
        ull v2 = warpMaxU64((ull)(b2a + 1));
        if (lane == 0) { gRed[wid][0] = v0; gRed[wid][1] = v1; gRed[wid][2] = v2; }
    }
    __syncthreads();
    if (wid == 0) {
        ull a0 = (lane < 16) ? gRed[lane][0] : 0;
        ull a1 = (lane < 16) ? gRed[lane][1] : 0;
        ull a2 = (lane < 16) ? gRed[lane][2] : 0;
        a0 = warpMaxU64(a0); a1 = warpMaxU64(a1); a2 = warpMaxU64(a2);
        if (lane == 0) { s_g[0] = a0; s_g[1] = a1; s_g[2] = a2; }
    }
    __syncthreads();

    // ---- final per-row triplet logic (thread 0)
    if (tid == 0) {
        long long R1 = (long long)s_g[0] - 1;
        long long R2c = (long long)s_g[1] - 1;
        long long R2a = (long long)s_g[2] - 1;
        int p_idx = (R1 >= 0) ? (4095 - (int)(R1 & 0xFFF)) : i;
        int p_new = (R2c >= 0) ? (4095 - (int)(R2c & 0xFFF))
                   : ((R2a >= 0) ? (4095 - (int)(R2a & 0xFFF)) : i);

        const float margin = 0.3f;
        int hn = s_sel[0];
        int first = 10;
        for (int t = 0; t < 10; t++) {
            if (prob[s_sel[1 + t]] >= thr) { first = t; break; }
        }
        int hn_new = s_sel[1 + first];

        float d_ip      = row[p_idx];
        float d_ihn     = row[hn];
        float d_ihn_new = row[hn_new];
        float d_ipnew   = row[p_new];
        bool conf_p  = prob[p_idx] >= thr;
        bool conf_hn = prob[hn]    >= thr;
        bool FN = (g_predArg[hn] == tgt_i);

        float ap = d_ip, an = d_ihn;
        bool bFN = conf_p && !conf_hn && FN;
        if (bFN) { ap = (d_ip + d_ihn) * 0.5f; an = d_ihn_new; }
        bool cRes = (!conf_p && conf_hn) || (!conf_p && !conf_hn && !FN);
        if (cRes) { an = (d_ip + d_ihn) * 0.5f; ap = d_ipnew; }
        bool inv = !conf_p && !conf_hn && FN;
        float c_conf = inv ? fmaxf(an - ap + margin, 0.f)
                           : fmaxf(ap - an + margin, 0.f);

        float apA = row[min(i + 32, NROW - 1)];
        float apB = row[max(i - 32, 0)];
        float apC = row[i];
        float cA = (fmaxf(apA - s_IC + margin, 0.f) + fmaxf(apA - s_VA + margin, 0.f)) * 0.5f;
        float cB = (fmaxf(apB - s_IC + margin, 0.f) + fmaxf(apB - s_VB + margin, 0.f)) * 0.5f;
        float cC = fmaxf(apC - s_IC + margin, 0.f);
        float c_unconf = (i < 32) ? cA : ((i < 64) ? cB : cC);

        bool confident_i = prob[i] >= thr;
        float c = confident_i ? c_conf : c_unconf;
        g_c[i] = c;
        g_flag[i] = (confident_i && (an >= ap)) ? 1 : 0;
    }
}

// ---------------- deterministic final reduction -------------------------------
__global__ __launch_bounds__(256) void final_kernel(
    const float* __restrict__ prob, const float* __restrict__ thrp,
    float* __restrict__ out, int out_size)
{
    __shared__ float sred[256];
    __shared__ int   ired[256], ired2[256];
    __shared__ int   s_j;
    int tid = threadIdx.x;
    float thr = *thrp;

    if (tid == 0) {
        int j = -1;
        for (int r = 0; r < 64; r++) if (!(prob[r] >= thr)) j = r;
        s_j = j;
    }
    __syncthreads();
    int j = s_j;

    float ls = 0.f; int cor = 0, cnt = 0;
    for (int r = tid; r < NROW; r += 256) {
        bool conf = prob[r] >= thr;
        bool ovr = (!conf) && (r < 64);
        bool keep = (r > j) && !ovr;
        if (keep) ls += g_c[r];
        if (conf) { cnt++; cor += g_flag[r]; }
    }
    sred[tid] = ls; ired[tid] = cor; ired2[tid] = cnt;
    __syncthreads();
    for (int s = 128; s > 0; s >>= 1) {
        if (tid < s) {
            sred[tid] += sred[tid + s];
            ired[tid] += ired[tid + s];
            ired2[tid] += ired2[tid + s];
        }
        __syncthreads();
    }
    if (tid == 0) {
        float loss = sred[0] + ((j >= 0) ? g_c[j] : 0.f);
        out[0] = loss * (1.f / (float)NROW);
        if (out_size > 1) out[1] = (float)ired[0];
        if (out_size > 2) out[2] = (float)ired2[0];
    }
    for (int t = 3 + tid; t < out_size; t += 256) out[t] = 0.f;
}

// ---------------- launch ------------------------------------------------------
extern "C" void kernel_launch(void* const* d_in, const int* in_sizes, int n_in,
                              void* d_out, int out_size) {
    const float* X       = (const float*)d_in[0];   // inputs (4096,1024) f32
    const float* P       = (const float*)d_in[1];   // prediction (4096,64) f32
    const int*   targets = (const int*)  d_in[2];   // targets (4096) i32
    const float* prob    = (const float*)d_in[4];   // prob (4096) f32
    const float* thr     = (const float*)d_in[5];   // threshold (1) f32
    float* out = (float*)d_out;

    sq_kernel<<<512, 256>>>(X);
    predarg_kernel<<<16, 256>>>(P);
    split_kernel<<<1024, 256>>>(X);
    dim3 g(NROW / 128, NROW / 128);
    gemm_bf16<<<g, 256>>>();
    row_kernel<<<NROW, 512>>>(prob, targets, thr);
    final_kernel<<<1, 256>>>(prob, thr, out, out_size);
}

// round 15
// speedup vs baseline: 3.9011x; 1.0072x over previous
#include <cuda_runtime.h>
#include <cuda_bf16.h>

#define NROW 4096
#define DIM  1024

// ---------------- scratch (device globals; no allocation allowed) -------------
__device__ float g_dist[NROW * NROW];            // 64 MB distance matrix
__device__ __nv_bfloat16 g_Ah[NROW * DIM];       // 8 MB hi split
__device__ __nv_bfloat16 g_Al[NROW * DIM];       // 8 MB lo split
__device__ float g_sq[NROW];
__device__ int   g_predArg[NROW];
__device__ float g_c[NROW];
__device__ int   g_flag[NROW];

typedef unsigned long long ull;

// ---------------- threefry2x32 (bit-exact vs JAX partitionable) ---------------
__device__ __forceinline__ unsigned rotl32(unsigned v, int r) {
    return (v << r) | (v >> (32 - r));
}

__device__ __forceinline__ uint2 threefry(unsigned k0, unsigned k1,
                                          unsigned x0, unsigned x1) {
    unsigned ks2 = k0 ^ k1 ^ 0x1BD11BDAu;
    x0 += k0; x1 += k1;
#define TFR(R) { x0 += x1; x1 = rotl32(x1, R); x1 ^= x0; }
    TFR(13) TFR(15) TFR(26) TFR(6)   x0 += k1;  x1 += ks2 + 1u;
    TFR(17) TFR(29) TFR(16) TFR(24)  x0 += ks2; x1 += k0  + 2u;
    TFR(13) TFR(15) TFR(26) TFR(6)   x0 += k0;  x1 += k1  + 3u;
    TFR(17) TFR(29) TFR(16) TFR(24)  x0 += k1;  x1 += ks2 + 4u;
    TFR(13) TFR(15) TFR(26) TFR(6)   x0 += ks2; x1 += k0  + 5u;
#undef TFR
    return make_uint2(x0, x1);
}

__device__ __forceinline__ unsigned gbits(uint2 key, unsigned m) {
    uint2 r = threefry(key.x, key.y, 0u, m);
    return r.x ^ r.y;
}

__device__ __forceinline__ ull warpMaxU64(ull x) {
#pragma unroll
    for (int o = 16; o > 0; o >>= 1) {
        ull t = __shfl_xor_sync(0xffffffffu, x, o);
        if (t > x) x = t;
    }
    return x;
}

// ---------------- small prep kernels -----------------------------------------
__global__ void sq_kernel(const float* __restrict__ X) {
    int warp = (blockIdx.x * blockDim.x + threadIdx.x) >> 5;
    int lane = threadIdx.x & 31;
    if (warp >= NROW) return;
    const float* xr = X + (size_t)warp * DIM;
    float s = 0.f;
    for (int k = lane; k < DIM; k += 32) { float v = xr[k]; s = fmaf(v, v, s); }
    for (int o = 16; o > 0; o >>= 1) s += __shfl_xor_sync(0xffffffffu, s, o);
    if (lane == 0) g_sq[warp] = s;
}

__global__ void predarg_kernel(const float* __restrict__ P) {
    int i = blockIdx.x * blockDim.x + threadIdx.x;
    if (i >= NROW) return;
    const float* pr = P + (size_t)i * 64;
    float bv = pr[0]; int bi = 0;
    for (int k = 1; k < 64; k++) { float v = pr[k]; if (v > bv) { bv = v; bi = k; } }
    g_predArg[i] = bi;
}

__global__ void split_kernel(const float* __restrict__ X) {
    int idx = blockIdx.x * blockDim.x + threadIdx.x;
    const float2* x2 = (const float2*)X;
    __nv_bfloat162* ah2 = (__nv_bfloat162*)g_Ah;
    __nv_bfloat162* al2 = (__nv_bfloat162*)g_Al;
    for (int t = idx; t < NROW * DIM / 2; t += gridDim.x * blockDim.x) {
        float2 v = x2[t];
        __nv_bfloat16 h0 = __float2bfloat16(v.x);
        __nv_bfloat16 h1 = __float2bfloat16(v.y);
        __nv_bfloat16 l0 = __float2bfloat16(v.x - __bfloat162float(h0));
        __nv_bfloat16 l1 = __float2bfloat16(v.y - __bfloat162float(h1));
        ah2[t] = __halves2bfloat162(h0, h1);
        al2[t] = __halves2bfloat162(l0, l1);
    }
}

// ---------------- tensor-core split-bf16 GEMM -> dist -------------------------
__device__ __forceinline__ void ldsm_x4(unsigned& r0, unsigned& r1,
                                        unsigned& r2, unsigned& r3, unsigned a) {
    asm volatile("ldmatrix.sync.aligned.m8n8.x4.shared.b16 {%0,%1,%2,%3}, [%4];"
                 : "=r"(r0), "=r"(r1), "=r"(r2), "=r"(r3) : "r"(a));
}
__device__ __forceinline__ void mma_bf16(float* d, const unsigned* a,
                                         unsigned b0, unsigned b1) {
    asm volatile(
        "mma.sync.aligned.m16n8k16.row.col.f32.bf16.bf16.f32 "
        "{%0,%1,%2,%3}, {%4,%5,%6,%7}, {%8,%9}, {%0,%1,%2,%3};"
        : "+f"(d[0]), "+f"(d[1]), "+f"(d[2]), "+f"(d[3])
        : "r"(a[0]), "r"(a[1]), "r"(a[2]), "r"(a[3]), "r"(b0), "r"(b1));
}
__device__ __forceinline__ void cp16(unsigned dst, const void* src) {
    asm volatile("cp.async.cg.shared.global [%0], [%1], 16;" :: "r"(dst), "l"(src));
}

// swizzled byte offset of (row, 16B-half) within a 128x32B tile
__device__ __forceinline__ unsigned sw_off(int row, int half) {
    return (unsigned)(row * 32 + (((half ^ (row >> 2)) & 1) << 4));
}
#define TOFF(s, t) (((s) * 4 + (t)) * 128 * 32)

__global__ __launch_bounds__(256, 2) void gemm_bf16() {
    __shared__ __align__(16) unsigned char smem[3 * 4 * 128 * 32]; // 48 KB exactly

    if (blockIdx.x < blockIdx.y) return;   // symmetry: upper blocks only (R12 form)
    const int bi = blockIdx.y * 128;
    const int bj = blockIdx.x * 128;
    const int tid = threadIdx.x;
    const int lane = tid & 31, wid = tid >> 5;
    const int wm = wid >> 2, wn = wid & 3;  // warp tile: 64(m) x 32(n)

    unsigned sbase = (unsigned)__cvta_generic_to_shared(smem);

    float acc[4][4][4];
#pragma unroll
    for (int a = 0; a < 4; a++)
#pragma unroll
        for (int b = 0; b < 4; b++)
#pragma unroll
            for (int c = 0; c < 4; c++) acc[a][b][c] = 0.f;

    const int lrow = tid >> 1, lhalf = tid & 1;   // loader mapping
    const __nv_bfloat16* srcA_h = g_Ah + (size_t)(bi + lrow) * DIM + lhalf * 8;
    const __nv_bfloat16* srcA_l = g_Al + (size_t)(bi + lrow) * DIM + lhalf * 8;
    const __nv_bfloat16* srcB_h = g_Ah + (size_t)(bj + lrow) * DIM + lhalf * 8;
    const __nv_bfloat16* srcB_l = g_Al + (size_t)(bj + lrow) * DIM + lhalf * 8;
    unsigned dsw = sw_off(lrow, lhalf);

#define LOAD_STAGE(k0, s) {                                   \
        cp16(sbase + TOFF(s, 0) + dsw, srcA_h + (k0));        \
        cp16(sbase + TOFF(s, 1) + dsw, srcA_l + (k0));        \
        cp16(sbase + TOFF(s, 2) + dsw, srcB_h + (k0));        \
        cp16(sbase + TOFF(s, 3) + dsw, srcB_l + (k0));        \
    }

    const int a_r = (lane & 7) + ((lane >> 3) & 1) * 8;
    const int a_h = (lane >> 4) & 1;
    const int b_mat = lane >> 3;
    const int b_n = ((b_mat >> 1) & 1) * 8 + (lane & 7);
    const int b_h = b_mat & 1;

    LOAD_STAGE(0, 0);
    asm volatile("cp.async.commit_group;");
    LOAD_STAGE(16, 1);
    asm volatile("cp.async.commit_group;");

    int cur = 0;
    for (int ks = 0; ks < 64; ks++) {
        __syncthreads();                    // all warps done with the slot we refill
        if (ks < 62) {
            int nxt = cur + 2; if (nxt >= 3) nxt -= 3;
            LOAD_STAGE((ks + 2) * 16, nxt);
        }
        asm volatile("cp.async.commit_group;");
        asm volatile("cp.async.wait_group 2;");   // stage `cur` (ks) is ready

        unsigned ah[4][4], bb[2][4];
#pragma unroll
        for (int mt = 0; mt < 4; mt++) {
            int r = wm * 64 + mt * 16 + a_r;
            ldsm_x4(ah[mt][0], ah[mt][1], ah[mt][2], ah[mt][3],
                    sbase + TOFF(cur, 0) + sw_off(r, a_h));
        }
#pragma unroll
        for (int p = 0; p < 2; p++) {
            int n = wn * 32 + p * 16 + b_n;
            ldsm_x4(bb[p][0], bb[p][1], bb[p][2], bb[p][3],
                    sbase + TOFF(cur, 2) + sw_off(n, b_h));
        }
        // hi*hi
#pragma unroll
        for (int mt = 0; mt < 4; mt++)
#pragma unroll
            for (int nt = 0; nt < 4; nt++)
                mma_bf16(acc[mt][nt], ah[mt], bb[nt >> 1][(nt & 1) * 2],
                         bb[nt >> 1][(nt & 1) * 2 + 1]);
        // lo*hi
        {
            unsigned al[4][4];
#pragma unroll
            for (int mt = 0; mt < 4; mt++) {
                int r = wm * 64 + mt * 16 + a_r;
                ldsm_x4(al[mt][0], al[mt][1], al[mt][2], al[mt][3],
                        sbase + TOFF(cur, 1) + sw_off(r, a_h));
            }
#pragma unroll
            for (int mt = 0; mt < 4; mt++)
#pragma unroll
                for (int nt = 0; nt < 4; nt++)
                    mma_bf16(acc[mt][nt], al[mt], bb[nt >> 1][(nt & 1) * 2],
                             bb[nt >> 1][(nt & 1) * 2 + 1]);
        }
        // hi*lo
#pragma unroll
        for (int p = 0; p < 2; p++) {
            int n = wn * 32 + p * 16 + b_n;
            ldsm_x4(bb[p][0], bb[p][1], bb[p][2], bb[p][3],
                    sbase + TOFF(cur, 3) + sw_off(n, b_h));
        }
#pragma unroll
        for (int mt = 0; mt < 4; mt++)
#pragma unroll
            for (int nt = 0; nt < 4; nt++)
                mma_bf16(acc[mt][nt], ah[mt], bb[nt >> 1][(nt & 1) * 2],
                         bb[nt >> 1][(nt & 1) * 2 + 1]);

        cur++; if (cur >= 3) cur = 0;
    }

    // epilogue: d2 -> sqrt -> store direct + mirror (g_sq read via L2)
    const bool diag = (blockIdx.x == blockIdx.y);
    const int r_b = wm * 64 + (lane >> 2);
    const int c_b = wn * 32 + (lane & 3) * 2;
#pragma unroll
    for (int mt = 0; mt < 4; mt++) {
#pragma unroll
        for (int h = 0; h < 2; h++) {
            int r = r_b + mt * 16 + h * 8;
            int ii = bi + r;
            float sqi = g_sq[ii];
#pragma unroll
            for (int nt = 0; nt < 4; nt++) {
                int c = c_b + nt * 8;
                int jj = bj + c;
                float v0 = sqrtf(fmaxf(sqi + g_sq[jj]     - 2.f * acc[mt][nt][2 * h],     1e-12f));
                float v1 = sqrtf(fmaxf(sqi + g_sq[jj + 1] - 2.f * acc[mt][nt][2 * h + 1], 1e-12f));
                float2 o; o.x = v0; o.y = v1;
                *reinterpret_cast<float2*>(&g_dist[(size_t)ii * NROW + jj]) = o;
                if (!diag) {
                    g_dist[(size_t)jj * NROW + ii] = v0;
                    g_dist[(size_t)(jj + 1) * NROW + ii] = v1;
                }
            }
        }
    }
}

// ---------------- per-row selection + triplet logic ---------------------------
// 512 threads = 16 warps. Per-lane Batcher sort + REDUX 2-stage extraction.

// descending compare-exchange: a keeps the larger
#define CX(a, b) { ull _mx = (a) > (b) ? (a) : (b); ull _mn = (a) > (b) ? (b) : (a); (a) = _mx; (b) = _mn; }
// Batcher odd-even mergesort, 8 elements, descending (k0 largest)
#define SORT8(k0,k1,k2,k3,k4,k5,k6,k7) {             \
    CX(k0,k1) CX(k2,k3) CX(k4,k5) CX(k6,k7)          \
    CX(k0,k2) CX(k1,k3) CX(k4,k6) CX(k5,k7)          \
    CX(k1,k2) CX(k5,k6)                              \
    CX(k0,k4) CX(k1,k5) CX(k2,k6) CX(k3,k7)          \
    CX(k2,k4) CX(k3,k5)                              \
    CX(k1,k2) CX(k3,k4) CX(k5,k6)                    \
}

__global__ __launch_bounds__(512) void row_kernel(
    const float* __restrict__ prob, const int* __restrict__ targets,
    const float* __restrict__ thrp)
{
    __shared__ float row[NROW];          // 16 KB
    __shared__ ull   icList[16][20];
    __shared__ ull   ngList[16][12];
    __shared__ ull   gRed[16][3];
    __shared__ ull   s_g[3];
    __shared__ float s_VA, s_VB, s_IC;
    __shared__ int   s_sel[12];

    const int i = blockIdx.x;
    const int tid = threadIdx.x;
    const int lane = tid & 31, wid = tid >> 5;
    const float thr = *thrp;
    const int tgt_i = __ldg(&targets[i]);
    const float* drow = g_dist + (size_t)i * NROW;

    for (int t = tid; t < NROW / 4; t += 512)
        ((float4*)row)[t] = ((const float4*)drow)[t];
    __syncthreads();

    ull k0, k1, k2, k3, k4, k5, k6, k7;

    // ---- IC: stable top-20 (desc) over cols [64,4096), bugged gather row[pos-64]
#define MKIC(kv, s) { int j = 64 + tid + ((s) << 9);                         \
        kv = (j < NROW) ? (((ull)__float_as_uint(row[j]) << 12)              \
                           | (unsigned)(4095 - j)) : 0ull; }
    MKIC(k0,0) MKIC(k1,1) MKIC(k2,2) MKIC(k3,3)
    MKIC(k4,4) MKIC(k5,5) MKIC(k6,6) MKIC(k7,7)
    SORT8(k0,k1,k2,k3,k4,k5,k6,k7)
    for (int it = 0; it < 20; it++) {
        unsigned hi = (unsigned)(k0 >> 12);
        unsigned m  = __reduce_max_sync(0xffffffffu, hi);
        unsigned lo = (hi == m) ? (unsigned)(k0 & 0xFFFull) : 0u;
        unsigned l  = __reduce_max_sync(0xffffffffu, lo);
        ull win = ((ull)m << 12) | l;
        if (lane == 0) icList[wid][it] = win;
        if (k0 == win) { k0=k1; k1=k2; k2=k3; k3=k4; k4=k5; k5=k6; k6=k7; k7=0; }
    }
    __syncthreads();

    // merge on warp 0; VA on warp 14; VB on warp 15 (concurrent)
    if (wid == 0) {
        int hp = 0;
        ull head = (lane < 16) ? icList[lane][0] : 0;
        float icsum = 0.f;
        for (int it = 0; it < 20; it++) {
            unsigned hi = (unsigned)(head >> 12);
            unsigned m  = __reduce_max_sync(0xffffffffu, hi);
            unsigned lo = (hi == m) ? (unsigned)(head & 0xFFFull) : 0u;
            unsigned l  = __reduce_max_sync(0xffffffffu, lo);
            ull win = ((ull)m << 12) | l;
            if (head == win && lane < 16) {
                hp++; head = (hp < 20) ? icList[lane][hp] : 0;
            }
            if (lane == 0) {
                int pos = 4095 - (int)(win & 0xFFFull);
                icsum += row[pos - 64];
            }
        }
        if (lane == 0) s_IC = icsum * (1.f / 20.f);
    } else if (wid >= 14) {
        int base = (wid - 14) * 32;
        unsigned bits = __float_as_uint(row[base + lane]);   // > 0 always
        unsigned removed = 0; float s = 0.f;
        for (int t = 0; t < 20; t++) {
            unsigned v = ((removed >> lane) & 1u) ? 0u : bits;
            unsigned M = __reduce_max_sync(0xffffffffu, v);
            unsigned L = __reduce_max_sync(0xffffffffu, (v == M) ? (31u - lane) : 0u);
            int bq = 31 - (int)L;
            removed |= 1u << bq;
            s += row[bq];                    // RELATIVE index gather (the bug)
        }
        if (lane == 0) { if (wid == 14) s_VA = s * (1.f / 20.f); else s_VB = s * (1.f / 20.f); }
    }

    // ---- 12 nearest negatives (stable ascending): key = ~bits (asc dist)
    unsigned memb = 0;   // per-thread class-membership bitmask for the 8 slots
#define MKNG(kv, s) { int j = tid + ((s) << 9);                              \
        int tj = __ldg(&targets[j]);                                         \
        bool same = (tj == tgt_i);                                           \
        if (same) memb |= 1u << (s);                                         \
        kv = (!same) ? (((ull)(~__float_as_uint(row[j])) << 12)              \
                              | (unsigned)(4095 - j)) : 0ull; }
    MKNG(k0,0) MKNG(k1,1) MKNG(k2,2) MKNG(k3,3)
    MKNG(k4,4) MKNG(k5,5) MKNG(k6,6) MKNG(k7,7)
    SORT8(k0,k1,k2,k3,k4,k5,k6,k7)
    for (int it = 0; it < 12; it++) {
        unsigned hi = (unsigned)(k0 >> 12);
        unsigned m  = __reduce_max_sync(0xffffffffu, hi);
        unsigned lo = (hi == m) ? (unsigned)(k0 & 0xFFFull) : 0u;
        unsigned l  = __reduce_max_sync(0xffffffffu, lo);
        ull win = ((ull)m << 12) | l;
        if (lane == 0) ngList[wid][it] = win;
        if (k0 == win) { k0=k1; k1=k2; k2=k3; k3=k4; k4=k5; k5=k6; k6=k7; k7=0; }
    }
    __syncthreads();
    if (wid == 0) {
        int hp = 0;
        ull head = (lane < 16) ? ngList[lane][0] : 0;
        for (int it = 0; it < 12; it++) {
            unsigned hi = (unsigned)(head >> 12);
            unsigned m  = __reduce_max_sync(0xffffffffu, hi);
            unsigned lo = (hi == m) ? (unsigned)(head & 0xFFFull) : 0u;
            unsigned l  = __reduce_max_sync(0xffffffffu, lo);
            ull win = ((ull)m << 12) | l;
            if (head == win && lane < 16) {
                hp++; head = (hp < 12) ? ngList[lane][hp] : 0;
            }
            if (lane == 0) s_sel[it] = 4095 - (int)(win & 0xFFFull);
        }
    }

    // ---- gumbel argmax over class members (monotone in folded bits)
    uint2 kg1 = threefry(0u, 42u, 0u, 0u);
    uint2 kg2 = threefry(0u, 42u, 0u, 1u);
    long long b1 = -1, b2c = -1, b2a = -1;
#pragma unroll
    for (int s = 0; s < 8; s++) {
        int j = tid + (s << 9);
        if (j == i || !((memb >> s) & 1u)) continue;
        unsigned m = (unsigned)(i * NROW + j);
        unsigned u1 = gbits(kg1, m) >> 9;
        unsigned u2 = gbits(kg2, m) >> 9;
        long long c1 = ((long long)u1 << 12) | (long long)(4095 - j);
        long long c2 = ((long long)u2 << 12) | (long long)(4095 - j);
        if (c1 > b1) b1 = c1;
        if (c2 > b2a) b2a = c2;
        if (prob[j] >= thr && c2 > b2c) b2c = c2;
    }
    {
        // 2-stage REDUX warp reductions (value hi-part, then index among ties)
#define WRED2(b, out) {                                                       \
        unsigned _h = (b >= 0) ? ((unsigned)((b) >> 12) + 1u) : 0u;           \
        unsigned _M = __reduce_max_sync(0xffffffffu, _h);                     \
        unsigned _l = (_h == _M && _M) ? (unsigned)((b) & 0xFFFll) : 0u;      \
        unsigned _L = __reduce_max_sync(0xffffffffu, _l);                     \
        out = _M ? ((((ull)(_M - 1u)) << 12) | _L) + 1ull : 0ull;             \
    }
        ull v0, v1, v2;
        WRED2(b1, v0); WRED2(b2c, v1); WRED2(b2a, v2);
        if (lane == 0) { gRed[wid][0] = v0; gRed[wid][1] = v1; gRed[wid][2] = v2; }
    }
    __syncthreads();
    if (wid == 0) {
        ull a0 = (lane < 16) ? gRed[lane][0] : 0;
        ull a1 = (lane < 16) ? gRed[lane][1] : 0;
        ull a2 = (lane < 16) ? gRed[lane][2] : 0;
        a0 = warpMaxU64(a0); a1 = warpMaxU64(a1); a2 = warpMaxU64(a2);
        if (lane == 0) { s_g[0] = a0; s_g[1] = a1; s_g[2] = a2; }
    }
    __syncthreads();

    // ---- final per-row triplet logic (thread 0)
    if (tid == 0) {
        long long R1 = (long long)s_g[0] - 1;
        long long R2c = (long long)s_g[1] - 1;
        long long R2a = (long long)s_g[2] - 1;
        int p_idx = (R1 >= 0) ? (4095 - (int)(R1 & 0xFFF)) : i;
        int p_new = (R2c >= 0) ? (4095 - (int)(R2c & 0xFFF))
                   : ((R2a >= 0) ? (4095 - (int)(R2a & 0xFFF)) : i);

        const float margin = 0.3f;
        int hn = s_sel[0];
        int first = 10;
        for (int t = 0; t < 10; t++) {
            if (prob[s_sel[1 + t]] >= thr) { first = t; break; }
        }
        int hn_new = s_sel[1 + first];

        float d_ip      = row[p_idx];
        float d_ihn     = row[hn];
        float d_ihn_new = row[hn_new];
        float d_ipnew   = row[p_new];
        bool conf_p  = prob[p_idx] >= thr;
        bool conf_hn = prob[hn]    >= thr;
        bool FN = (g_predArg[hn] == tgt_i);

        float ap = d_ip, an = d_ihn;
        bool bFN = conf_p && !conf_hn && FN;
        if (bFN) { ap = (d_ip + d_ihn) * 0.5f; an = d_ihn_new; }
        bool cRes = (!conf_p && conf_hn) || (!conf_p && !conf_hn && !FN);
        if (cRes) { an = (d_ip + d_ihn) * 0.5f; ap = d_ipnew; }
        bool inv = !conf_p && !conf_hn && FN;
        float c_conf = inv ? fmaxf(an - ap + margin, 0.f)
                           : fmaxf(ap - an + margin, 0.f);

        float apA = row[min(i + 32, NROW - 1)];
        float apB = row[max(i - 32, 0)];
        float apC = row[i];
        float cA = (fmaxf(apA - s_IC + margin, 0.f) + fmaxf(apA - s_VA + margin, 0.f)) * 0.5f;
        float cB = (fmaxf(apB - s_IC + margin, 0.f) + fmaxf(apB - s_VB + margin, 0.f)) * 0.5f;
        float cC = fmaxf(apC - s_IC + margin, 0.f);
        float c_unconf = (i < 32) ? cA : ((i < 64) ? cB : cC);

        bool confident_i = prob[i] >= thr;
        float c = confident_i ? c_conf : c_unconf;
        g_c[i] = c;
        g_flag[i] = (confident_i && (an >= ap)) ? 1 : 0;
    }
}

// ---------------- deterministic final reduction -------------------------------
__global__ __launch_bounds__(256) void final_kernel(
    const float* __restrict__ prob, const float* __restrict__ thrp,
    float* __restrict__ out, int out_size)
{
    __shared__ float sred[256];
    __shared__ int   ired[256], ired2[256];
    __shared__ int   s_j;
    int tid = threadIdx.x;
    float thr = *thrp;

    if (tid == 0) {
        int j = -1;
        for (int r = 0; r < 64; r++) if (!(prob[r] >= thr)) j = r;
        s_j = j;
    }
    __syncthreads();
    int j = s_j;

    float ls = 0.f; int cor = 0, cnt = 0;
    for (int r = tid; r < NROW; r += 256) {
        bool conf = prob[r] >= thr;
        bool ovr = (!conf) && (r < 64);
        bool keep = (r > j) && !ovr;
        if (keep) ls += g_c[r];
        if (conf) { cnt++; cor += g_flag[r]; }
    }
    sred[tid] = ls; ired[tid] = cor; ired2[tid] = cnt;
    __syncthreads();
    for (int s = 128; s > 0; s >>= 1) {
        if (tid < s) {
            sred[tid] += sred[tid + s];
            ired[tid] += ired[tid + s];
            ired2[tid] += ired2[tid + s];
        }
        __syncthreads();
    }
    if (tid == 0) {
        float loss = sred[0] + ((j >= 0) ? g_c[j] : 0.f);
        out[0] = loss * (1.f / (float)NROW);
        if (out_size > 1) out[1] = (float)ired[0];
        if (out_size > 2) out[2] = (float)ired2[0];
    }
    for (int t = 3 + tid; t < out_size; t += 256) out[t] = 0.f;
}

// ---------------- launch ------------------------------------------------------
extern "C" void kernel_launch(void* const* d_in, const int* in_sizes, int n_in,
                              void* d_out, int out_size) {
    const float* X       = (const float*)d_in[0];   // inputs (4096,1024) f32
    const float* P       = (const float*)d_in[1];   // prediction (4096,64) f32
    const int*   targets = (const int*)  d_in[2];   // targets (4096) i32
    const float* prob    = (const float*)d_in[4];   // prob (4096) f32
    const float* thr     = (const float*)d_in[5];   // threshold (1) f32
    float* out = (float*)d_out;

    sq_kernel<<<512, 256>>>(X);
    predarg_kernel<<<16, 256>>>(P);
    split_kernel<<<1024, 256>>>(X);
    dim3 g(NROW / 128, NROW / 128);
    gemm_bf16<<<g, 256>>>();                      // 2D grid, early-exit lower tri
    row_kernel<<<NROW, 512>>>(prob, targets, thr);
    final_kernel<<<1, 256>>>(prob, thr, out, out_size);
}